// round 9
// baseline (speedup 1.0000x reference)
#include <cuda_runtime.h>
#include <cuda_bf16.h>
#include <cstdint>

#define NTOT   12288
#define DIN    512
#define DIM    512
#define HEADS  8
#define DHEAD  64
#define NBATCH 32

// ======================= PTX helpers (sm_80 ISA, valid at compute_103) ==========
__device__ __forceinline__ uint32_t smem_u32(const void* p) {
    uint32_t a;
    asm("{ .reg .u64 t; cvta.to.shared.u64 t, %1; cvt.u32.u64 %0, t; }" : "=r"(a) : "l"(p));
    return a;
}
__device__ __forceinline__ void ldsm4(uint32_t* r, uint32_t addr) {
    asm volatile("ldmatrix.sync.aligned.m8n8.x4.shared.b16 {%0,%1,%2,%3}, [%4];"
        : "=r"(r[0]), "=r"(r[1]), "=r"(r[2]), "=r"(r[3]) : "r"(addr));
}
__device__ __forceinline__ void ldsm4t(uint32_t* r, uint32_t addr) {
    asm volatile("ldmatrix.sync.aligned.m8n8.x4.trans.shared.b16 {%0,%1,%2,%3}, [%4];"
        : "=r"(r[0]), "=r"(r[1]), "=r"(r[2]), "=r"(r[3]) : "r"(addr));
}
__device__ __forceinline__ void mma16816(float* c, const uint32_t* a,
                                         uint32_t b0, uint32_t b1) {
    asm volatile("mma.sync.aligned.m16n8k16.row.col.f32.bf16.bf16.f32 "
        "{%0,%1,%2,%3}, {%4,%5,%6,%7}, {%8,%9}, {%0,%1,%2,%3};"
        : "+f"(c[0]), "+f"(c[1]), "+f"(c[2]), "+f"(c[3])
        : "r"(a[0]), "r"(a[1]), "r"(a[2]), "r"(a[3]), "r"(b0), "r"(b1));
}
__device__ __forceinline__ void cpa16(uint32_t s, const void* g) {
    asm volatile("cp.async.cg.shared.global [%0], [%1], 16;" :: "r"(s), "l"(g));
}
__device__ __forceinline__ void cpa16z(uint32_t s, const void* g, bool p) {
    int sz = p ? 16 : 0;
    asm volatile("cp.async.cg.shared.global [%0], [%1], 16, %2;" :: "r"(s), "l"(g), "r"(sz));
}
#define CP_COMMIT() asm volatile("cp.async.commit_group;" ::: "memory")
#define CP_WAIT(n)  asm volatile("cp.async.wait_group %0;" :: "n"(n) : "memory")

__device__ __forceinline__ uint32_t packhi(float x, float y) {
    __nv_bfloat162 h = __floats2bfloat162_rn(x, y);
    return *(uint32_t*)&h;
}
__device__ __forceinline__ uint32_t packlo(float x, float y, uint32_t hi) {
    __nv_bfloat162 h = *(__nv_bfloat162*)&hi;
    __nv_bfloat162 l = __floats2bfloat162_rn(x - __bfloat162float(h.x),
                                             y - __bfloat162float(h.y));
    return *(uint32_t*)&l;
}

// ======================= scratch =================================================
__device__ __nv_bfloat16 g_ahi[NTOT * DIN];
__device__ __nv_bfloat16 g_alo[NTOT * DIN];
__device__ __nv_bfloat16 g_wthi[4 * DIN * DIM];   // [mat][n][k]
__device__ __nv_bfloat16 g_wtlo[4 * DIN * DIM];
__device__ __nv_bfloat16 g_qhi[NTOT * DIM];
__device__ __nv_bfloat16 g_qlo[NTOT * DIM];
__device__ __nv_bfloat16 g_khi[NTOT * DIM];
__device__ __nv_bfloat16 g_klo[NTOT * DIM];
__device__ __nv_bfloat16 g_vhi[NTOT * DIM];
__device__ __nv_bfloat16 g_vlo[NTOT * DIM];
__device__ int g_starts[NBATCH + 1];

// ======================= starts ==================================================
__global__ void starts_kernel(const int* __restrict__ src) {
    int b = threadIdx.x;
    if (b > NBATCH) return;
    int lo = 0, hi = NTOT;
    while (lo < hi) { int mid = (lo + hi) >> 1; if (src[mid] < b) lo = mid + 1; else hi = mid; }
    g_starts[b] = lo;
}

// ======================= LayerNorm -> split bf16 =================================
__global__ void __launch_bounds__(128) ln_kernel(const float* __restrict__ z,
                                                 const float* __restrict__ gamma,
                                                 const float* __restrict__ beta) {
    __shared__ float red[8];
    const int row = blockIdx.x;
    const int t = threadIdx.x;
    float4 v = ((const float4*)(z + (size_t)row * DIN))[t];
    float s  = v.x + v.y + v.z + v.w;
    float ss = v.x*v.x + v.y*v.y + v.z*v.z + v.w*v.w;
    #pragma unroll
    for (int off = 16; off; off >>= 1) {
        s  += __shfl_xor_sync(0xffffffffu, s,  off);
        ss += __shfl_xor_sync(0xffffffffu, ss, off);
    }
    const int w = t >> 5;
    if ((t & 31) == 0) { red[w] = s; red[4 + w] = ss; }
    __syncthreads();
    s  = red[0] + red[1] + red[2] + red[3];
    ss = red[4] + red[5] + red[6] + red[7];
    const float mu  = s * (1.0f / DIN);
    const float var = ss * (1.0f / DIN) - mu * mu;
    const float inv = rsqrtf(var + 1e-5f);
    float4 g  = ((const float4*)gamma)[t];
    float4 be = ((const float4*)beta)[t];
    float o[4];
    o[0] = (v.x - mu) * inv * g.x + be.x;
    o[1] = (v.y - mu) * inv * g.y + be.y;
    o[2] = (v.z - mu) * inv * g.z + be.z;
    o[3] = (v.w - mu) * inv * g.w + be.w;
    size_t base = (size_t)row * DIN + t * 4;
    uint32_t h0 = packhi(o[0], o[1]), h1 = packhi(o[2], o[3]);
    *(uint32_t*)&g_ahi[base]     = h0;
    *(uint32_t*)&g_ahi[base + 2] = h1;
    *(uint32_t*)&g_alo[base]     = packlo(o[0], o[1], h0);
    *(uint32_t*)&g_alo[base + 2] = packlo(o[2], o[3], h1);
}

// ======================= weight transpose + split ================================
__global__ void __launch_bounds__(256) wconv_kernel(const float* __restrict__ Wq,
                                                    const float* __restrict__ Wk,
                                                    const float* __restrict__ Wv,
                                                    const float* __restrict__ Wo) {
    __shared__ float t[32][33];
    const float* W = blockIdx.z == 0 ? Wq : blockIdx.z == 1 ? Wk : blockIdx.z == 2 ? Wv : Wo;
    const int bx = blockIdx.x, by = blockIdx.y;
    const int tx = threadIdx.x, ty = threadIdx.y;    // 32 x 8
    #pragma unroll
    for (int i = 0; i < 4; i++)
        t[ty + 8 * i][tx] = W[(size_t)(by * 32 + ty + 8 * i) * DIM + bx * 32 + tx];
    __syncthreads();
    size_t mbase = (size_t)blockIdx.z * DIN * DIM;
    #pragma unroll
    for (int i = 0; i < 4; i++) {
        int n = bx * 32 + ty + 8 * i;
        int k = by * 32 + tx;
        float v = t[tx][ty + 8 * i];
        __nv_bfloat16 hi = __float2bfloat16(v);
        __nv_bfloat16 lo = __float2bfloat16(v - __bfloat162float(hi));
        g_wthi[mbase + (size_t)n * DIN + k] = hi;
        g_wtlo[mbase + (size_t)n * DIN + k] = lo;
    }
}

// ======================= split-bf16 GEMM: R5 compute + cp.async double buffer ====
// C[12288,512] = (Ahi+Alo)@(Whi+Wlo)  CTA 128x128, k-chunk 64, 8 warps (32x64).
// 2-stage cp.async pipeline; compute phase identical to the measured-good R3/R5.
#define GLDS 72
#define G_TILE_B  (128 * GLDS * 2)     // 18432 B per tile
#define G_STAGE_B (4 * G_TILE_B)       // 73728 B
#define G_SMEM_TOT (2 * G_STAGE_B)     // 147456 B -> 1 CTA/SM

// EPI 0: write bf16 hi/lo pairs (per-mat).  EPI 1: write fp32 + bias.
template<int EPI>
__global__ void __launch_bounds__(256, 1)
gemm_mma(const __nv_bfloat16* __restrict__ Ahi, const __nv_bfloat16* __restrict__ Alo,
         const __nv_bfloat16* __restrict__ Wthi, const __nv_bfloat16* __restrict__ Wtlo,
         __nv_bfloat16* h0, __nv_bfloat16* l0, __nv_bfloat16* h1, __nv_bfloat16* l1,
         __nv_bfloat16* h2, __nv_bfloat16* l2, float* fout, const float* __restrict__ bias) {
    extern __shared__ char smem[];
    const uint32_t sb = smem_u32(smem);
    const int tid  = threadIdx.x;
    const int wid  = tid >> 5;
    const int lane = tid & 31;
    const int mwarp = wid & 3;           // warp m offset = mwarp*32
    const int nwarp = wid >> 2;          // warp n offset = nwarp*64
    const int nBase = blockIdx.x * 128;
    const int mBase = blockIdx.y * 128;
    const int mat = blockIdx.z;
    const int lrow = lane & 15;
    const int lcol = (lane >> 4) * 8;

    __nv_bfloat16* ohi = (mat == 0) ? h0 : (mat == 1) ? h1 : h2;
    __nv_bfloat16* olo = (mat == 0) ? l0 : (mat == 1) ? l1 : l2;

    const __nv_bfloat16* gsrc[4] = {
        Ahi + (size_t)mBase * DIN,
        Alo + (size_t)mBase * DIN,
        Wthi + (size_t)mat * DIN * DIM + (size_t)nBase * DIN,
        Wtlo + (size_t)mat * DIN * DIM + (size_t)nBase * DIN };

    float acc[2][8][4];
    #pragma unroll
    for (int a = 0; a < 2; a++)
        #pragma unroll
        for (int b = 0; b < 8; b++)
            #pragma unroll
            for (int c = 0; c < 4; c++) acc[a][b][c] = 0.f;

    const int lr  = tid >> 1;           // 0..127  (row)
    const int lj0 = (tid & 1) * 4;      // 0 or 4  (16B-unit column base)

    // stage loader: 4 tiles x [128 rows x 64 bf16]; 16 cp.async per thread
    auto load_chunk = [&](int st, int kb) {
        const uint32_t sbase = sb + st * G_STAGE_B;
        #pragma unroll
        for (int t = 0; t < 4; t++) {
            const __nv_bfloat16* gp = gsrc[t] + kb + (size_t)lr * DIN + lj0 * 8;
            const uint32_t sp = sbase + t * G_TILE_B + lr * (GLDS * 2) + lj0 * 16;
            #pragma unroll
            for (int j = 0; j < 4; j++)
                cpa16(sp + j * 16, gp + j * 8);
        }
    };

    load_chunk(0, 0); CP_COMMIT();

    for (int chunk = 0; chunk < 8; chunk++) {
        if (chunk < 7) { load_chunk((chunk + 1) & 1, (chunk + 1) * 64); CP_COMMIT(); CP_WAIT(1); }
        else           { CP_WAIT(0); }
        __syncthreads();
        const uint32_t sbs = sb + (chunk & 1) * G_STAGE_B;

        #pragma unroll
        for (int ks = 0; ks < 4; ks++) {
            const int kk = ks * 16 + lcol;
            uint32_t ah[2][4], al[2][4];
            #pragma unroll
            for (int mt = 0; mt < 2; mt++) {
                uint32_t off = (uint32_t)((mwarp * 32 + mt * 16 + lrow) * GLDS + kk) * 2;
                ldsm4(ah[mt], sbs + off);
                ldsm4(al[mt], sbs + G_TILE_B + off);
            }
            #pragma unroll
            for (int nb = 0; nb < 4; nb++) {
                uint32_t off = (uint32_t)((nwarp * 64 + nb * 16 + lrow) * GLDS + kk) * 2;
                uint32_t bh[4], bl[4];
                ldsm4(bh, sbs + 2 * G_TILE_B + off);
                ldsm4(bl, sbs + 3 * G_TILE_B + off);
                #pragma unroll
                for (int mt = 0; mt < 2; mt++) {
                    float* c0 = acc[mt][2 * nb];
                    float* c1 = acc[mt][2 * nb + 1];
                    mma16816(c0, ah[mt], bh[0], bh[2]);
                    mma16816(c0, ah[mt], bl[0], bl[2]);
                    mma16816(c0, al[mt], bh[0], bh[2]);
                    mma16816(c1, ah[mt], bh[1], bh[3]);
                    mma16816(c1, ah[mt], bl[1], bl[3]);
                    mma16816(c1, al[mt], bh[1], bh[3]);
                }
            }
        }
        __syncthreads();
    }

    const int erow = lane >> 2;
    const int ecol = (lane & 3) * 2;
    #pragma unroll
    for (int mt = 0; mt < 2; mt++) {
        int r0 = mBase + mwarp * 32 + mt * 16 + erow;
        #pragma unroll
        for (int n8 = 0; n8 < 8; n8++) {
            int col = nBase + nwarp * 64 + n8 * 8 + ecol;
            float c0 = acc[mt][n8][0], c1 = acc[mt][n8][1];
            float c2 = acc[mt][n8][2], c3 = acc[mt][n8][3];
            if (EPI == 1) {
                float2 bb = *(const float2*)&bias[col];
                *(float2*)&fout[(size_t)r0 * DIM + col]       = make_float2(c0 + bb.x, c1 + bb.y);
                *(float2*)&fout[(size_t)(r0 + 8) * DIM + col] = make_float2(c2 + bb.x, c3 + bb.y);
            } else {
                uint32_t p0 = packhi(c0, c1), p1 = packhi(c2, c3);
                *(uint32_t*)&ohi[(size_t)r0 * DIM + col]       = p0;
                *(uint32_t*)&olo[(size_t)r0 * DIM + col]       = packlo(c0, c1, p0);
                *(uint32_t*)&ohi[(size_t)(r0 + 8) * DIM + col] = p1;
                *(uint32_t*)&olo[(size_t)(r0 + 8) * DIM + col] = packlo(c2, c3, p1);
            }
        }
    }
}

// ======================= tensor-core flash attention (R4/R5, unchanged) ==========
#define AP 72
#define AT_B (64 * AP * 2)                 // 9216
#define A_SMEM (2 * AT_B + 2 * 4 * AT_B)   // 92160

__global__ void __launch_bounds__(128)
attn_kernel(const __nv_bfloat16* __restrict__ qhi, const __nv_bfloat16* __restrict__ qlo,
            const __nv_bfloat16* __restrict__ khi, const __nv_bfloat16* __restrict__ klo,
            const __nv_bfloat16* __restrict__ vhi, const __nv_bfloat16* __restrict__ vlo,
            __nv_bfloat16* __restrict__ ohi, __nv_bfloat16* __restrict__ olo) {
    extern __shared__ char smem[];
    const uint32_t sb = smem_u32(smem);
    const int qt = blockIdx.x, h = blockIdx.y, b = blockIdx.z;
    const int s0 = g_starts[b];
    const int ng = g_starts[b + 1] - s0;
    const int q0 = qt * 64;
    if (q0 >= ng) return;
    const int tid = threadIdx.x;
    const int w = tid >> 5, lane = tid & 31;
    const int lrow = lane & 15, lcol = (lane >> 4) * 8;

    const uint32_t sQhi = sb, sQlo = sb + AT_B;

    {
        const size_t gb = (size_t)(s0 + q0) * DIM + h * DHEAD;
        #pragma unroll
        for (int r = 0; r < 4; r++) {
            int idx = tid + r * 128;
            int m = idx >> 3, j = idx & 7;
            bool p = (q0 + m) < ng;
            uint32_t so = (uint32_t)(m * AP + j * 8) * 2;
            cpa16z(sQhi + so, qhi + gb + (size_t)m * DIM + j * 8, p);
            cpa16z(sQlo + so, qlo + gb + (size_t)m * DIM + j * 8, p);
        }
    }

    const __nv_bfloat16* kvsrc[4] = { khi, klo, vhi, vlo };
    auto load_kv = [&](int st, int kb) {
        uint32_t sbase = sb + 2 * AT_B + st * 4 * AT_B;
        const size_t gb = (size_t)(s0 + kb) * DIM + h * DHEAD;
        #pragma unroll
        for (int t = 0; t < 4; t++)
            #pragma unroll
            for (int r = 0; r < 4; r++) {
                int idx = tid + r * 128;
                int m = idx >> 3, j = idx & 7;
                bool p = (kb + m) < ng;
                cpa16z(sbase + t * AT_B + (uint32_t)(m * AP + j * 8) * 2,
                       kvsrc[t] + gb + (size_t)m * DIM + j * 8, p);
            }
    };

    load_kv(0, 0); CP_COMMIT();

    float sv[8][4], ov[8][4];
    #pragma unroll
    for (int j = 0; j < 8; j++)
        #pragma unroll
        for (int c = 0; c < 4; c++) ov[j][c] = 0.f;
    float rm0 = -1e30f, rm1 = -1e30f, rl0 = 0.f, rl1 = 0.f;

    const int nchunks = (ng + 63) >> 6;
    for (int c = 0; c < nchunks; c++) {
        if (c + 1 < nchunks) { load_kv((c + 1) & 1, (c + 1) * 64); CP_COMMIT(); CP_WAIT(1); }
        else                 { CP_WAIT(0); }
        __syncthreads();
        const uint32_t sK  = sb + 2 * AT_B + (c & 1) * 4 * AT_B;
        const uint32_t sKl = sK + AT_B, sVh = sK + 2 * AT_B, sVl = sK + 3 * AT_B;

        #pragma unroll
        for (int j = 0; j < 8; j++)
            #pragma unroll
            for (int cc = 0; cc < 4; cc++) sv[j][cc] = 0.f;
        #pragma unroll
        for (int ks = 0; ks < 4; ks++) {
            const int kk = ks * 16 + lcol;
            uint32_t qh[4], ql[4];
            uint32_t qoff = (uint32_t)((w * 16 + lrow) * AP + kk) * 2;
            ldsm4(qh, sQhi + qoff);
            ldsm4(ql, sQlo + qoff);
            #pragma unroll
            for (int n16 = 0; n16 < 4; n16++) {
                uint32_t off = (uint32_t)((n16 * 16 + lrow) * AP + kk) * 2;
                uint32_t kh[4], kl[4];
                ldsm4(kh, sK + off);
                ldsm4(kl, sKl + off);
                float* c0 = sv[2 * n16];
                float* c1 = sv[2 * n16 + 1];
                mma16816(c0, qh, kh[0], kh[2]);
                mma16816(c0, qh, kl[0], kl[2]);
                mma16816(c0, ql, kh[0], kh[2]);
                mma16816(c1, qh, kh[1], kh[3]);
                mma16816(c1, qh, kl[1], kl[3]);
                mma16816(c1, ql, kh[1], kh[3]);
            }
        }

        const int kb = c * 64;
        #pragma unroll
        for (int j = 0; j < 8; j++) {
            int col = kb + j * 8 + (lane & 3) * 2;
            bool v0 = col < ng, v1 = (col + 1) < ng;
            sv[j][0] = v0 ? sv[j][0] * 0.125f : -1e30f;
            sv[j][1] = v1 ? sv[j][1] * 0.125f : -1e30f;
            sv[j][2] = v0 ? sv[j][2] * 0.125f : -1e30f;
            sv[j][3] = v1 ? sv[j][3] * 0.125f : -1e30f;
        }
        float m0 = -1e30f, m1 = -1e30f;
        #pragma unroll
        for (int j = 0; j < 8; j++) {
            m0 = fmaxf(m0, fmaxf(sv[j][0], sv[j][1]));
            m1 = fmaxf(m1, fmaxf(sv[j][2], sv[j][3]));
        }
        m0 = fmaxf(m0, __shfl_xor_sync(0xffffffffu, m0, 1));
        m0 = fmaxf(m0, __shfl_xor_sync(0xffffffffu, m0, 2));
        m1 = fmaxf(m1, __shfl_xor_sync(0xffffffffu, m1, 1));
        m1 = fmaxf(m1, __shfl_xor_sync(0xffffffffu, m1, 2));
        float nm0 = fmaxf(rm0, m0), nm1 = fmaxf(rm1, m1);
        float sc0 = __expf(rm0 - nm0), sc1 = __expf(rm1 - nm1);
        rm0 = nm0; rm1 = nm1;
        float l0 = 0.f, l1 = 0.f;
        #pragma unroll
        for (int j = 0; j < 8; j++) {
            sv[j][0] = __expf(sv[j][0] - nm0); l0 += sv[j][0];
            sv[j][1] = __expf(sv[j][1] - nm0); l0 += sv[j][1];
            sv[j][2] = __expf(sv[j][2] - nm1); l1 += sv[j][2];
            sv[j][3] = __expf(sv[j][3] - nm1); l1 += sv[j][3];
        }
        l0 += __shfl_xor_sync(0xffffffffu, l0, 1);
        l0 += __shfl_xor_sync(0xffffffffu, l0, 2);
        l1 += __shfl_xor_sync(0xffffffffu, l1, 1);
        l1 += __shfl_xor_sync(0xffffffffu, l1, 2);
        rl0 = rl0 * sc0 + l0;
        rl1 = rl1 * sc1 + l1;
        #pragma unroll
        for (int j = 0; j < 8; j++) {
            ov[j][0] *= sc0; ov[j][1] *= sc0;
            ov[j][2] *= sc1; ov[j][3] *= sc1;
        }

        #pragma unroll
        for (int ks = 0; ks < 4; ks++) {
            uint32_t ahi[4], alo[4];
            ahi[0] = packhi(sv[2 * ks][0], sv[2 * ks][1]);
            alo[0] = packlo(sv[2 * ks][0], sv[2 * ks][1], ahi[0]);
            ahi[1] = packhi(sv[2 * ks][2], sv[2 * ks][3]);
            alo[1] = packlo(sv[2 * ks][2], sv[2 * ks][3], ahi[1]);
            ahi[2] = packhi(sv[2 * ks + 1][0], sv[2 * ks + 1][1]);
            alo[2] = packlo(sv[2 * ks + 1][0], sv[2 * ks + 1][1], ahi[2]);
            ahi[3] = packhi(sv[2 * ks + 1][2], sv[2 * ks + 1][3]);
            alo[3] = packlo(sv[2 * ks + 1][2], sv[2 * ks + 1][3], ahi[3]);
            #pragma unroll
            for (int d16 = 0; d16 < 4; d16++) {
                uint32_t off = (uint32_t)((ks * 16 + lrow) * AP + d16 * 16 + lcol) * 2;
                uint32_t vh[4], vl[4];
                ldsm4t(vh, sVh + off);
                ldsm4t(vl, sVl + off);
                float* c0 = ov[2 * d16];
                float* c1 = ov[2 * d16 + 1];
                mma16816(c0, ahi, vh[0], vh[1]);
                mma16816(c0, ahi, vl[0], vl[1]);
                mma16816(c0, alo, vh[0], vh[1]);
                mma16816(c1, ahi, vh[2], vh[3]);
                mma16816(c1, ahi, vl[2], vl[3]);
                mma16816(c1, alo, vh[2], vh[3]);
            }
        }
        __syncthreads();
    }

    const float inv0 = 1.f / rl0, inv1 = 1.f / rl1;
    const int m0r = q0 + w * 16 + (lane >> 2);
    const bool v0 = m0r < ng, v1 = (m0r + 8) < ng;
    const size_t rb0 = (size_t)(s0 + m0r) * DIM + h * DHEAD;
    const size_t rb1 = rb0 + 8 * DIM;
    #pragma unroll
    for (int j = 0; j < 8; j++) {
        int d = j * 8 + (lane & 3) * 2;
        if (v0) {
            float x = ov[j][0] * inv0, y = ov[j][1] * inv0;
            uint32_t p = packhi(x, y);
            *(uint32_t*)&ohi[rb0 + d] = p;
            *(uint32_t*)&olo[rb0 + d] = packlo(x, y, p);
        }
        if (v1) {
            float x = ov[j][2] * inv1, y = ov[j][3] * inv1;
            uint32_t p = packhi(x, y);
            *(uint32_t*)&ohi[rb1 + d] = p;
            *(uint32_t*)&olo[rb1 + d] = packlo(x, y, p);
        }
    }
}

// ======================= launch ==================================================
extern "C" void kernel_launch(void* const* d_in, const int* in_sizes, int n_in,
                              void* d_out, int out_size) {
    const float* z     = (const float*)d_in[0];
    const int*   src   = (const int*)  d_in[1];
    const float* gamma = (const float*)d_in[2];
    const float* beta  = (const float*)d_in[3];
    const float* Wq    = (const float*)d_in[4];
    const float* Wk    = (const float*)d_in[5];
    const float* Wv    = (const float*)d_in[6];
    const float* Wo    = (const float*)d_in[7];
    const float* bo    = (const float*)d_in[8];
    float* out = (float*)d_out;

    cudaFuncSetAttribute(attn_kernel, cudaFuncAttributeMaxDynamicSharedMemorySize, A_SMEM);
    cudaFuncSetAttribute(gemm_mma<0>, cudaFuncAttributeMaxDynamicSharedMemorySize, G_SMEM_TOT);
    cudaFuncSetAttribute(gemm_mma<1>, cudaFuncAttributeMaxDynamicSharedMemorySize, G_SMEM_TOT);

    __nv_bfloat16 *ahi_p, *alo_p, *wthi_p, *wtlo_p;
    __nv_bfloat16 *qh, *ql, *kh, *kl, *vh, *vl;
    cudaGetSymbolAddress((void**)&ahi_p,  g_ahi);
    cudaGetSymbolAddress((void**)&alo_p,  g_alo);
    cudaGetSymbolAddress((void**)&wthi_p, g_wthi);
    cudaGetSymbolAddress((void**)&wtlo_p, g_wtlo);
    cudaGetSymbolAddress((void**)&qh, g_qhi);
    cudaGetSymbolAddress((void**)&ql, g_qlo);
    cudaGetSymbolAddress((void**)&kh, g_khi);
    cudaGetSymbolAddress((void**)&kl, g_klo);
    cudaGetSymbolAddress((void**)&vh, g_vhi);
    cudaGetSymbolAddress((void**)&vl, g_vlo);

    starts_kernel<<<1, 64>>>(src);
    ln_kernel<<<NTOT, 128>>>(z, gamma, beta);
    wconv_kernel<<<dim3(16, 16, 4), dim3(32, 8)>>>(Wq, Wk, Wv, Wo);

    // fused Q/K/V projections -> bf16 hi/lo outputs (2-stage cp.async pipeline)
    gemm_mma<0><<<dim3(4, 96, 3), 256, G_SMEM_TOT>>>(
        ahi_p, alo_p, wthi_p, wtlo_p, qh, ql, kh, kl, vh, vl, nullptr, nullptr);

    attn_kernel<<<dim3(8, HEADS, NBATCH), 128, A_SMEM>>>(qh, ql, kh, kl, vh, vl, ahi_p, alo_p);

    // output projection (fp32 + bias)
    gemm_mma<1><<<dim3(4, 96, 1), 256, G_SMEM_TOT>>>(
        ahi_p, alo_p, wthi_p + 3 * DIN * DIM, wtlo_p + 3 * DIN * DIM,
        nullptr, nullptr, nullptr, nullptr, nullptr, nullptr, out, bo);
}

// round 10
// speedup vs baseline: 1.2825x; 1.2825x over previous
#include <cuda_runtime.h>
#include <cuda_bf16.h>
#include <cstdint>

#define NTOT   12288
#define DIN    512
#define DIM    512
#define HEADS  8
#define DHEAD  64
#define NBATCH 32

// ======================= PTX helpers (sm_80 ISA, valid at compute_103) ==========
__device__ __forceinline__ uint32_t smem_u32(const void* p) {
    uint32_t a;
    asm("{ .reg .u64 t; cvta.to.shared.u64 t, %1; cvt.u32.u64 %0, t; }" : "=r"(a) : "l"(p));
    return a;
}
__device__ __forceinline__ void ldsm4(uint32_t* r, uint32_t addr) {
    asm volatile("ldmatrix.sync.aligned.m8n8.x4.shared.b16 {%0,%1,%2,%3}, [%4];"
        : "=r"(r[0]), "=r"(r[1]), "=r"(r[2]), "=r"(r[3]) : "r"(addr));
}
__device__ __forceinline__ void ldsm4t(uint32_t* r, uint32_t addr) {
    asm volatile("ldmatrix.sync.aligned.m8n8.x4.trans.shared.b16 {%0,%1,%2,%3}, [%4];"
        : "=r"(r[0]), "=r"(r[1]), "=r"(r[2]), "=r"(r[3]) : "r"(addr));
}
__device__ __forceinline__ void mma16816(float* c, const uint32_t* a,
                                         uint32_t b0, uint32_t b1) {
    asm volatile("mma.sync.aligned.m16n8k16.row.col.f32.bf16.bf16.f32 "
        "{%0,%1,%2,%3}, {%4,%5,%6,%7}, {%8,%9}, {%0,%1,%2,%3};"
        : "+f"(c[0]), "+f"(c[1]), "+f"(c[2]), "+f"(c[3])
        : "r"(a[0]), "r"(a[1]), "r"(a[2]), "r"(a[3]), "r"(b0), "r"(b1));
}
__device__ __forceinline__ void cpa16z(uint32_t s, const void* g, bool p) {
    int sz = p ? 16 : 0;
    asm volatile("cp.async.cg.shared.global [%0], [%1], 16, %2;" :: "r"(s), "l"(g), "r"(sz));
}
#define CP_COMMIT() asm volatile("cp.async.commit_group;" ::: "memory")
#define CP_WAIT(n)  asm volatile("cp.async.wait_group %0;" :: "n"(n) : "memory")

__device__ __forceinline__ uint32_t packhi(float x, float y) {
    __nv_bfloat162 h = __floats2bfloat162_rn(x, y);
    return *(uint32_t*)&h;
}
__device__ __forceinline__ uint32_t packlo(float x, float y, uint32_t hi) {
    __nv_bfloat162 h = *(__nv_bfloat162*)&hi;
    __nv_bfloat162 l = __floats2bfloat162_rn(x - __bfloat162float(h.x),
                                             y - __bfloat162float(h.y));
    return *(uint32_t*)&l;
}

// ======================= scratch =================================================
__device__ __nv_bfloat16 g_ahi[NTOT * DIN];
__device__ __nv_bfloat16 g_alo[NTOT * DIN];
__device__ __nv_bfloat16 g_wthi[4 * DIN * DIM];   // [mat][n][k]
__device__ __nv_bfloat16 g_wtlo[4 * DIN * DIM];
__device__ __nv_bfloat16 g_qhi[NTOT * DIM];
__device__ __nv_bfloat16 g_qlo[NTOT * DIM];
__device__ __nv_bfloat16 g_khi[NTOT * DIM];
__device__ __nv_bfloat16 g_klo[NTOT * DIM];
__device__ __nv_bfloat16 g_vhi[NTOT * DIM];
__device__ __nv_bfloat16 g_vlo[NTOT * DIM];
__device__ int g_starts[NBATCH + 1];

// ======================= starts ==================================================
__global__ void starts_kernel(const int* __restrict__ src) {
    int b = threadIdx.x;
    if (b > NBATCH) return;
    int lo = 0, hi = NTOT;
    while (lo < hi) { int mid = (lo + hi) >> 1; if (src[mid] < b) lo = mid + 1; else hi = mid; }
    g_starts[b] = lo;
}

// ======================= LayerNorm -> split bf16 =================================
__global__ void __launch_bounds__(128) ln_kernel(const float* __restrict__ z,
                                                 const float* __restrict__ gamma,
                                                 const float* __restrict__ beta) {
    __shared__ float red[8];
    const int row = blockIdx.x;
    const int t = threadIdx.x;
    float4 v = ((const float4*)(z + (size_t)row * DIN))[t];
    float s  = v.x + v.y + v.z + v.w;
    float ss = v.x*v.x + v.y*v.y + v.z*v.z + v.w*v.w;
    #pragma unroll
    for (int off = 16; off; off >>= 1) {
        s  += __shfl_xor_sync(0xffffffffu, s,  off);
        ss += __shfl_xor_sync(0xffffffffu, ss, off);
    }
    const int w = t >> 5;
    if ((t & 31) == 0) { red[w] = s; red[4 + w] = ss; }
    __syncthreads();
    s  = red[0] + red[1] + red[2] + red[3];
    ss = red[4] + red[5] + red[6] + red[7];
    const float mu  = s * (1.0f / DIN);
    const float var = ss * (1.0f / DIN) - mu * mu;
    const float inv = rsqrtf(var + 1e-5f);
    float4 g  = ((const float4*)gamma)[t];
    float4 be = ((const float4*)beta)[t];
    float o[4];
    o[0] = (v.x - mu) * inv * g.x + be.x;
    o[1] = (v.y - mu) * inv * g.y + be.y;
    o[2] = (v.z - mu) * inv * g.z + be.z;
    o[3] = (v.w - mu) * inv * g.w + be.w;
    size_t base = (size_t)row * DIN + t * 4;
    uint32_t h0 = packhi(o[0], o[1]), h1 = packhi(o[2], o[3]);
    *(uint32_t*)&g_ahi[base]     = h0;
    *(uint32_t*)&g_ahi[base + 2] = h1;
    *(uint32_t*)&g_alo[base]     = packlo(o[0], o[1], h0);
    *(uint32_t*)&g_alo[base + 2] = packlo(o[2], o[3], h1);
}

// ======================= weight transpose + split ================================
__global__ void __launch_bounds__(256) wconv_kernel(const float* __restrict__ Wq,
                                                    const float* __restrict__ Wk,
                                                    const float* __restrict__ Wv,
                                                    const float* __restrict__ Wo) {
    __shared__ float t[32][33];
    const float* W = blockIdx.z == 0 ? Wq : blockIdx.z == 1 ? Wk : blockIdx.z == 2 ? Wv : Wo;
    const int bx = blockIdx.x, by = blockIdx.y;
    const int tx = threadIdx.x, ty = threadIdx.y;    // 32 x 8
    #pragma unroll
    for (int i = 0; i < 4; i++)
        t[ty + 8 * i][tx] = W[(size_t)(by * 32 + ty + 8 * i) * DIM + bx * 32 + tx];
    __syncthreads();
    size_t mbase = (size_t)blockIdx.z * DIN * DIM;
    #pragma unroll
    for (int i = 0; i < 4; i++) {
        int n = bx * 32 + ty + 8 * i;
        int k = by * 32 + tx;
        float v = t[tx][ty + 8 * i];
        __nv_bfloat16 hi = __float2bfloat16(v);
        __nv_bfloat16 lo = __float2bfloat16(v - __bfloat162float(hi));
        g_wthi[mbase + (size_t)n * DIN + k] = hi;
        g_wtlo[mbase + (size_t)n * DIN + k] = lo;
    }
}

// ======================= mma.sync split-bf16 GEMM (R5 + anti-phase chunks) =======
// C[12288,512] = (Ahi+Alo)@(Whi+Wlo)  CTA tile 128x128, k-chunk 64, 8 warps.
// Co-resident CTAs (bid, bid+148) visit chunks 4-out-of-phase so one loads while
// the other computes. Sum order per CTA is fixed -> deterministic.
#define GLDS 72
#define G_TILE_B (128 * GLDS * 2)      // 18432 B per tile
#define G_SMEM_TOT (4 * G_TILE_B)      // 73728 B -> 2 CTAs/SM

// EPI 0: write bf16 hi/lo pairs (per-mat).  EPI 1: write fp32 + bias.
template<int EPI>
__global__ void __launch_bounds__(256, 2)
gemm_mma(const __nv_bfloat16* __restrict__ Ahi, const __nv_bfloat16* __restrict__ Alo,
         const __nv_bfloat16* __restrict__ Wthi, const __nv_bfloat16* __restrict__ Wtlo,
         __nv_bfloat16* h0, __nv_bfloat16* l0, __nv_bfloat16* h1, __nv_bfloat16* l1,
         __nv_bfloat16* h2, __nv_bfloat16* l2, float* fout, const float* __restrict__ bias) {
    extern __shared__ char smem[];
    const uint32_t sb = smem_u32(smem);
    const int tid  = threadIdx.x;
    const int wid  = tid >> 5;
    const int lane = tid & 31;
    const int mwarp = wid & 3;           // warp m offset = mwarp*32
    const int nwarp = wid >> 2;          // warp n offset = nwarp*64
    const int nBase = blockIdx.x * 128;
    const int mBase = blockIdx.y * 128;
    const int mat = blockIdx.z;
    const int lrow = lane & 15;
    const int lcol = (lane >> 4) * 8;

    // anti-phase: co-resident wave partners (bid, bid+148) get offsets 0 / 4
    const int bid = blockIdx.x + gridDim.x * (blockIdx.y + gridDim.y * blockIdx.z);
    const int cph = ((bid / 148) & 1) * 4;

    __nv_bfloat16* ohi = (mat == 0) ? h0 : (mat == 1) ? h1 : h2;
    __nv_bfloat16* olo = (mat == 0) ? l0 : (mat == 1) ? l1 : l2;

    const __nv_bfloat16* gsrc[4] = {
        Ahi + (size_t)mBase * DIN,
        Alo + (size_t)mBase * DIN,
        Wthi + (size_t)mat * DIN * DIM + (size_t)nBase * DIN,
        Wtlo + (size_t)mat * DIN * DIM + (size_t)nBase * DIN };

    float acc[2][8][4];
    #pragma unroll
    for (int a = 0; a < 2; a++)
        #pragma unroll
        for (int b = 0; b < 8; b++)
            #pragma unroll
            for (int c = 0; c < 4; c++) acc[a][b][c] = 0.f;

    for (int ci = 0; ci < 8; ci++) {
        const int kb = ((ci + cph) & 7) * 64;
        #pragma unroll
        for (int t = 0; t < 4; t++) {
            const __nv_bfloat16* gp = gsrc[t] + kb;
            char* sp = smem + t * G_TILE_B;
            #pragma unroll
            for (int r = 0; r < 4; r++) {
                int idx = tid + r * 256;          // 0..1023
                int row = idx >> 3;               // 0..127
                int j   = idx & 7;                // 16B units (8 bf16)
                uint4 v = *(const uint4*)(gp + (size_t)row * DIN + j * 8);
                *(uint4*)(sp + row * (GLDS * 2) + j * 16) = v;
            }
        }
        __syncthreads();

        #pragma unroll
        for (int ks = 0; ks < 4; ks++) {
            const int kk = ks * 16 + lcol;
            uint32_t ah[2][4], al[2][4];
            #pragma unroll
            for (int mt = 0; mt < 2; mt++) {
                uint32_t off = (uint32_t)((mwarp * 32 + mt * 16 + lrow) * GLDS + kk) * 2;
                ldsm4(ah[mt], sb + off);
                ldsm4(al[mt], sb + G_TILE_B + off);
            }
            #pragma unroll
            for (int nb = 0; nb < 4; nb++) {
                uint32_t off = (uint32_t)((nwarp * 64 + nb * 16 + lrow) * GLDS + kk) * 2;
                uint32_t bh[4], bl[4];
                ldsm4(bh, sb + 2 * G_TILE_B + off);
                ldsm4(bl, sb + 3 * G_TILE_B + off);
                #pragma unroll
                for (int mt = 0; mt < 2; mt++) {
                    float* c0 = acc[mt][2 * nb];
                    float* c1 = acc[mt][2 * nb + 1];
                    mma16816(c0, ah[mt], bh[0], bh[2]);
                    mma16816(c0, ah[mt], bl[0], bl[2]);
                    mma16816(c0, al[mt], bh[0], bh[2]);
                    mma16816(c1, ah[mt], bh[1], bh[3]);
                    mma16816(c1, ah[mt], bl[1], bl[3]);
                    mma16816(c1, al[mt], bh[1], bh[3]);
                }
            }
        }
        __syncthreads();
    }

    const int erow = lane >> 2;
    const int ecol = (lane & 3) * 2;
    #pragma unroll
    for (int mt = 0; mt < 2; mt++) {
        int r0 = mBase + mwarp * 32 + mt * 16 + erow;
        #pragma unroll
        for (int n8 = 0; n8 < 8; n8++) {
            int col = nBase + nwarp * 64 + n8 * 8 + ecol;
            float c0 = acc[mt][n8][0], c1 = acc[mt][n8][1];
            float c2 = acc[mt][n8][2], c3 = acc[mt][n8][3];
            if (EPI == 1) {
                float2 bb = *(const float2*)&bias[col];
                *(float2*)&fout[(size_t)r0 * DIM + col]       = make_float2(c0 + bb.x, c1 + bb.y);
                *(float2*)&fout[(size_t)(r0 + 8) * DIM + col] = make_float2(c2 + bb.x, c3 + bb.y);
            } else {
                uint32_t p0 = packhi(c0, c1), p1 = packhi(c2, c3);
                *(uint32_t*)&ohi[(size_t)r0 * DIM + col]       = p0;
                *(uint32_t*)&olo[(size_t)r0 * DIM + col]       = packlo(c0, c1, p0);
                *(uint32_t*)&ohi[(size_t)(r0 + 8) * DIM + col] = p1;
                *(uint32_t*)&olo[(size_t)(r0 + 8) * DIM + col] = packlo(c2, c3, p1);
            }
        }
    }
}

// ======================= tensor-core flash attention (R4/R5, unchanged) ==========
#define AP 72
#define AT_B (64 * AP * 2)                 // 9216
#define A_SMEM (2 * AT_B + 2 * 4 * AT_B)   // 92160

__global__ void __launch_bounds__(128)
attn_kernel(const __nv_bfloat16* __restrict__ qhi, const __nv_bfloat16* __restrict__ qlo,
            const __nv_bfloat16* __restrict__ khi, const __nv_bfloat16* __restrict__ klo,
            const __nv_bfloat16* __restrict__ vhi, const __nv_bfloat16* __restrict__ vlo,
            __nv_bfloat16* __restrict__ ohi, __nv_bfloat16* __restrict__ olo) {
    extern __shared__ char smem[];
    const uint32_t sb = smem_u32(smem);
    const int qt = blockIdx.x, h = blockIdx.y, b = blockIdx.z;
    const int s0 = g_starts[b];
    const int ng = g_starts[b + 1] - s0;
    const int q0 = qt * 64;
    if (q0 >= ng) return;
    const int tid = threadIdx.x;
    const int w = tid >> 5, lane = tid & 31;
    const int lrow = lane & 15, lcol = (lane >> 4) * 8;

    const uint32_t sQhi = sb, sQlo = sb + AT_B;

    {
        const size_t gb = (size_t)(s0 + q0) * DIM + h * DHEAD;
        #pragma unroll
        for (int r = 0; r < 4; r++) {
            int idx = tid + r * 128;
            int m = idx >> 3, j = idx & 7;
            bool p = (q0 + m) < ng;
            uint32_t so = (uint32_t)(m * AP + j * 8) * 2;
            cpa16z(sQhi + so, qhi + gb + (size_t)m * DIM + j * 8, p);
            cpa16z(sQlo + so, qlo + gb + (size_t)m * DIM + j * 8, p);
        }
    }

    const __nv_bfloat16* kvsrc[4] = { khi, klo, vhi, vlo };
    auto load_kv = [&](int st, int kb) {
        uint32_t sbase = sb + 2 * AT_B + st * 4 * AT_B;
        const size_t gb = (size_t)(s0 + kb) * DIM + h * DHEAD;
        #pragma unroll
        for (int t = 0; t < 4; t++)
            #pragma unroll
            for (int r = 0; r < 4; r++) {
                int idx = tid + r * 128;
                int m = idx >> 3, j = idx & 7;
                bool p = (kb + m) < ng;
                cpa16z(sbase + t * AT_B + (uint32_t)(m * AP + j * 8) * 2,
                       kvsrc[t] + gb + (size_t)m * DIM + j * 8, p);
            }
    };

    load_kv(0, 0); CP_COMMIT();

    float sv[8][4], ov[8][4];
    #pragma unroll
    for (int j = 0; j < 8; j++)
        #pragma unroll
        for (int c = 0; c < 4; c++) ov[j][c] = 0.f;
    float rm0 = -1e30f, rm1 = -1e30f, rl0 = 0.f, rl1 = 0.f;

    const int nchunks = (ng + 63) >> 6;
    for (int c = 0; c < nchunks; c++) {
        if (c + 1 < nchunks) { load_kv((c + 1) & 1, (c + 1) * 64); CP_COMMIT(); CP_WAIT(1); }
        else                 { CP_WAIT(0); }
        __syncthreads();
        const uint32_t sK  = sb + 2 * AT_B + (c & 1) * 4 * AT_B;
        const uint32_t sKl = sK + AT_B, sVh = sK + 2 * AT_B, sVl = sK + 3 * AT_B;

        #pragma unroll
        for (int j = 0; j < 8; j++)
            #pragma unroll
            for (int cc = 0; cc < 4; cc++) sv[j][cc] = 0.f;
        #pragma unroll
        for (int ks = 0; ks < 4; ks++) {
            const int kk = ks * 16 + lcol;
            uint32_t qh[4], ql[4];
            uint32_t qoff = (uint32_t)((w * 16 + lrow) * AP + kk) * 2;
            ldsm4(qh, sQhi + qoff);
            ldsm4(ql, sQlo + qoff);
            #pragma unroll
            for (int n16 = 0; n16 < 4; n16++) {
                uint32_t off = (uint32_t)((n16 * 16 + lrow) * AP + kk) * 2;
                uint32_t kh[4], kl[4];
                ldsm4(kh, sK + off);
                ldsm4(kl, sKl + off);
                float* c0 = sv[2 * n16];
                float* c1 = sv[2 * n16 + 1];
                mma16816(c0, qh, kh[0], kh[2]);
                mma16816(c0, qh, kl[0], kl[2]);
                mma16816(c0, ql, kh[0], kh[2]);
                mma16816(c1, qh, kh[1], kh[3]);
                mma16816(c1, qh, kl[1], kl[3]);
                mma16816(c1, ql, kh[1], kh[3]);
            }
        }

        const int kb = c * 64;
        #pragma unroll
        for (int j = 0; j < 8; j++) {
            int col = kb + j * 8 + (lane & 3) * 2;
            bool v0 = col < ng, v1 = (col + 1) < ng;
            sv[j][0] = v0 ? sv[j][0] * 0.125f : -1e30f;
            sv[j][1] = v1 ? sv[j][1] * 0.125f : -1e30f;
            sv[j][2] = v0 ? sv[j][2] * 0.125f : -1e30f;
            sv[j][3] = v1 ? sv[j][3] * 0.125f : -1e30f;
        }
        float m0 = -1e30f, m1 = -1e30f;
        #pragma unroll
        for (int j = 0; j < 8; j++) {
            m0 = fmaxf(m0, fmaxf(sv[j][0], sv[j][1]));
            m1 = fmaxf(m1, fmaxf(sv[j][2], sv[j][3]));
        }
        m0 = fmaxf(m0, __shfl_xor_sync(0xffffffffu, m0, 1));
        m0 = fmaxf(m0, __shfl_xor_sync(0xffffffffu, m0, 2));
        m1 = fmaxf(m1, __shfl_xor_sync(0xffffffffu, m1, 1));
        m1 = fmaxf(m1, __shfl_xor_sync(0xffffffffu, m1, 2));
        float nm0 = fmaxf(rm0, m0), nm1 = fmaxf(rm1, m1);
        float sc0 = __expf(rm0 - nm0), sc1 = __expf(rm1 - nm1);
        rm0 = nm0; rm1 = nm1;
        float l0 = 0.f, l1 = 0.f;
        #pragma unroll
        for (int j = 0; j < 8; j++) {
            sv[j][0] = __expf(sv[j][0] - nm0); l0 += sv[j][0];
            sv[j][1] = __expf(sv[j][1] - nm0); l0 += sv[j][1];
            sv[j][2] = __expf(sv[j][2] - nm1); l1 += sv[j][2];
            sv[j][3] = __expf(sv[j][3] - nm1); l1 += sv[j][3];
        }
        l0 += __shfl_xor_sync(0xffffffffu, l0, 1);
        l0 += __shfl_xor_sync(0xffffffffu, l0, 2);
        l1 += __shfl_xor_sync(0xffffffffu, l1, 1);
        l1 += __shfl_xor_sync(0xffffffffu, l1, 2);
        rl0 = rl0 * sc0 + l0;
        rl1 = rl1 * sc1 + l1;
        #pragma unroll
        for (int j = 0; j < 8; j++) {
            ov[j][0] *= sc0; ov[j][1] *= sc0;
            ov[j][2] *= sc1; ov[j][3] *= sc1;
        }

        #pragma unroll
        for (int ks = 0; ks < 4; ks++) {
            uint32_t ahi[4], alo[4];
            ahi[0] = packhi(sv[2 * ks][0], sv[2 * ks][1]);
            alo[0] = packlo(sv[2 * ks][0], sv[2 * ks][1], ahi[0]);
            ahi[1] = packhi(sv[2 * ks][2], sv[2 * ks][3]);
            alo[1] = packlo(sv[2 * ks][2], sv[2 * ks][3], ahi[1]);
            ahi[2] = packhi(sv[2 * ks + 1][0], sv[2 * ks + 1][1]);
            alo[2] = packlo(sv[2 * ks + 1][0], sv[2 * ks + 1][1], ahi[2]);
            ahi[3] = packhi(sv[2 * ks + 1][2], sv[2 * ks + 1][3]);
            alo[3] = packlo(sv[2 * ks + 1][2], sv[2 * ks + 1][3], ahi[3]);
            #pragma unroll
            for (int d16 = 0; d16 < 4; d16++) {
                uint32_t off = (uint32_t)((ks * 16 + lrow) * AP + d16 * 16 + lcol) * 2;
                uint32_t vh[4], vl[4];
                ldsm4t(vh, sVh + off);
                ldsm4t(vl, sVl + off);
                float* c0 = ov[2 * d16];
                float* c1 = ov[2 * d16 + 1];
                mma16816(c0, ahi, vh[0], vh[1]);
                mma16816(c0, ahi, vl[0], vl[1]);
                mma16816(c0, alo, vh[0], vh[1]);
                mma16816(c1, ahi, vh[2], vh[3]);
                mma16816(c1, ahi, vl[2], vl[3]);
                mma16816(c1, alo, vh[2], vh[3]);
            }
        }
        __syncthreads();
    }

    const float inv0 = 1.f / rl0, inv1 = 1.f / rl1;
    const int m0r = q0 + w * 16 + (lane >> 2);
    const bool v0 = m0r < ng, v1 = (m0r + 8) < ng;
    const size_t rb0 = (size_t)(s0 + m0r) * DIM + h * DHEAD;
    const size_t rb1 = rb0 + 8 * DIM;
    #pragma unroll
    for (int j = 0; j < 8; j++) {
        int d = j * 8 + (lane & 3) * 2;
        if (v0) {
            float x = ov[j][0] * inv0, y = ov[j][1] * inv0;
            uint32_t p = packhi(x, y);
            *(uint32_t*)&ohi[rb0 + d] = p;
            *(uint32_t*)&olo[rb0 + d] = packlo(x, y, p);
        }
        if (v1) {
            float x = ov[j][2] * inv1, y = ov[j][3] * inv1;
            uint32_t p = packhi(x, y);
            *(uint32_t*)&ohi[rb1 + d] = p;
            *(uint32_t*)&olo[rb1 + d] = packlo(x, y, p);
        }
    }
}

// ======================= launch ==================================================
extern "C" void kernel_launch(void* const* d_in, const int* in_sizes, int n_in,
                              void* d_out, int out_size) {
    const float* z     = (const float*)d_in[0];
    const int*   src   = (const int*)  d_in[1];
    const float* gamma = (const float*)d_in[2];
    const float* beta  = (const float*)d_in[3];
    const float* Wq    = (const float*)d_in[4];
    const float* Wk    = (const float*)d_in[5];
    const float* Wv    = (const float*)d_in[6];
    const float* Wo    = (const float*)d_in[7];
    const float* bo    = (const float*)d_in[8];
    float* out = (float*)d_out;

    cudaFuncSetAttribute(attn_kernel, cudaFuncAttributeMaxDynamicSharedMemorySize, A_SMEM);
    cudaFuncSetAttribute(gemm_mma<0>, cudaFuncAttributeMaxDynamicSharedMemorySize, G_SMEM_TOT);
    cudaFuncSetAttribute(gemm_mma<1>, cudaFuncAttributeMaxDynamicSharedMemorySize, G_SMEM_TOT);

    __nv_bfloat16 *ahi_p, *alo_p, *wthi_p, *wtlo_p;
    __nv_bfloat16 *qh, *ql, *kh, *kl, *vh, *vl;
    cudaGetSymbolAddress((void**)&ahi_p,  g_ahi);
    cudaGetSymbolAddress((void**)&alo_p,  g_alo);
    cudaGetSymbolAddress((void**)&wthi_p, g_wthi);
    cudaGetSymbolAddress((void**)&wtlo_p, g_wtlo);
    cudaGetSymbolAddress((void**)&qh, g_qhi);
    cudaGetSymbolAddress((void**)&ql, g_qlo);
    cudaGetSymbolAddress((void**)&kh, g_khi);
    cudaGetSymbolAddress((void**)&kl, g_klo);
    cudaGetSymbolAddress((void**)&vh, g_vhi);
    cudaGetSymbolAddress((void**)&vl, g_vlo);

    starts_kernel<<<1, 64>>>(src);
    ln_kernel<<<NTOT, 128>>>(z, gamma, beta);
    wconv_kernel<<<dim3(16, 16, 4), dim3(32, 8)>>>(Wq, Wk, Wv, Wo);

    // fused Q/K/V projections -> bf16 hi/lo outputs (R5 shape + anti-phase chunks)
    gemm_mma<0><<<dim3(4, 96, 3), 256, G_SMEM_TOT>>>(
        ahi_p, alo_p, wthi_p, wtlo_p, qh, ql, kh, kl, vh, vl, nullptr, nullptr);

    attn_kernel<<<dim3(8, HEADS, NBATCH), 128, A_SMEM>>>(qh, ql, kh, kl, vh, vl, ahi_p, alo_p);

    // output projection (fp32 + bias)
    gemm_mma<1><<<dim3(4, 96, 1), 256, G_SMEM_TOT>>>(
        ahi_p, alo_p, wthi_p + 3 * DIN * DIM, wtlo_p + 3 * DIN * DIM,
        nullptr, nullptr, nullptr, nullptr, nullptr, nullptr, out, bo);
}

// round 12
// speedup vs baseline: 1.5321x; 1.1946x over previous
#include <cuda_runtime.h>
#include <cuda_fp16.h>
#include <cstdint>

#define NTOT   12288
#define DIN    512
#define DIM    512
#define HEADS  8
#define DHEAD  64
#define NBATCH 32

// ======================= PTX helpers (sm_80 ISA, valid at compute_103) ==========
__device__ __forceinline__ uint32_t smem_u32(const void* p) {
    uint32_t a;
    asm("{ .reg .u64 t; cvta.to.shared.u64 t, %1; cvt.u32.u64 %0, t; }" : "=r"(a) : "l"(p));
    return a;
}
__device__ __forceinline__ void ldsm4(uint32_t* r, uint32_t addr) {
    asm volatile("ldmatrix.sync.aligned.m8n8.x4.shared.b16 {%0,%1,%2,%3}, [%4];"
        : "=r"(r[0]), "=r"(r[1]), "=r"(r[2]), "=r"(r[3]) : "r"(addr));
}
__device__ __forceinline__ void ldsm4t(uint32_t* r, uint32_t addr) {
    asm volatile("ldmatrix.sync.aligned.m8n8.x4.trans.shared.b16 {%0,%1,%2,%3}, [%4];"
        : "=r"(r[0]), "=r"(r[1]), "=r"(r[2]), "=r"(r[3]) : "r"(addr));
}
// fp16 MMA: products exact in fp32 accumulate (11x11 mantissa bits)
__device__ __forceinline__ void mma16816(float* c, const uint32_t* a,
                                         uint32_t b0, uint32_t b1) {
    asm volatile("mma.sync.aligned.m16n8k16.row.col.f32.f16.f16.f32 "
        "{%0,%1,%2,%3}, {%4,%5,%6,%7}, {%8,%9}, {%0,%1,%2,%3};"
        : "+f"(c[0]), "+f"(c[1]), "+f"(c[2]), "+f"(c[3])
        : "r"(a[0]), "r"(a[1]), "r"(a[2]), "r"(a[3]), "r"(b0), "r"(b1));
}
__device__ __forceinline__ void cpa16z(uint32_t s, const void* g, bool p) {
    int sz = p ? 16 : 0;
    asm volatile("cp.async.cg.shared.global [%0], [%1], 16, %2;" :: "r"(s), "l"(g), "r"(sz));
}
#define CP_COMMIT() asm volatile("cp.async.commit_group;" ::: "memory")
#define CP_WAIT(n)  asm volatile("cp.async.wait_group %0;" :: "n"(n) : "memory")

__device__ __forceinline__ uint32_t packhi(float x, float y) {
    __half2 h = __floats2half2_rn(x, y);
    return *(uint32_t*)&h;
}
__device__ __forceinline__ uint32_t packlo(float x, float y, uint32_t hi) {
    __half2 h = *(__half2*)&hi;
    __half2 l = __floats2half2_rn(x - __half2float(h.x), y - __half2float(h.y));
    return *(uint32_t*)&l;
}

// ======================= scratch =================================================
__device__ __half g_ahi[NTOT * DIN];
__device__ __half g_alo[NTOT * DIN];
__device__ __half g_wt [4 * DIN * DIM];   // [mat][n][k], single fp16
__device__ __half g_qhi[NTOT * DIM];
__device__ __half g_qlo[NTOT * DIM];
__device__ __half g_khi[NTOT * DIM];
__device__ __half g_klo[NTOT * DIM];
__device__ __half g_vhi[NTOT * DIM];
__device__ __half g_vlo[NTOT * DIM];
__device__ int g_starts[NBATCH + 1];

// ======================= starts ==================================================
__global__ void starts_kernel(const int* __restrict__ src) {
    int b = threadIdx.x;
    if (b > NBATCH) return;
    int lo = 0, hi = NTOT;
    while (lo < hi) { int mid = (lo + hi) >> 1; if (src[mid] < b) lo = mid + 1; else hi = mid; }
    g_starts[b] = lo;
}

// ======================= LayerNorm -> split fp16 =================================
__global__ void __launch_bounds__(128) ln_kernel(const float* __restrict__ z,
                                                 const float* __restrict__ gamma,
                                                 const float* __restrict__ beta) {
    __shared__ float red[8];
    const int row = blockIdx.x;
    const int t = threadIdx.x;
    float4 v = ((const float4*)(z + (size_t)row * DIN))[t];
    float s  = v.x + v.y + v.z + v.w;
    float ss = v.x*v.x + v.y*v.y + v.z*v.z + v.w*v.w;
    #pragma unroll
    for (int off = 16; off; off >>= 1) {
        s  += __shfl_xor_sync(0xffffffffu, s,  off);
        ss += __shfl_xor_sync(0xffffffffu, ss, off);
    }
    const int w = t >> 5;
    if ((t & 31) == 0) { red[w] = s; red[4 + w] = ss; }
    __syncthreads();
    s  = red[0] + red[1] + red[2] + red[3];
    ss = red[4] + red[5] + red[6] + red[7];
    const float mu  = s * (1.0f / DIN);
    const float var = ss * (1.0f / DIN) - mu * mu;
    const float inv = rsqrtf(var + 1e-5f);
    float4 g  = ((const float4*)gamma)[t];
    float4 be = ((const float4*)beta)[t];
    float o[4];
    o[0] = (v.x - mu) * inv * g.x + be.x;
    o[1] = (v.y - mu) * inv * g.y + be.y;
    o[2] = (v.z - mu) * inv * g.z + be.z;
    o[3] = (v.w - mu) * inv * g.w + be.w;
    size_t base = (size_t)row * DIN + t * 4;
    uint32_t h0 = packhi(o[0], o[1]), h1 = packhi(o[2], o[3]);
    *(uint32_t*)&g_ahi[base]     = h0;
    *(uint32_t*)&g_ahi[base + 2] = h1;
    *(uint32_t*)&g_alo[base]     = packlo(o[0], o[1], h0);
    *(uint32_t*)&g_alo[base + 2] = packlo(o[2], o[3], h1);
}

// ======================= weight transpose (single fp16) ==========================
__global__ void __launch_bounds__(256) wconv_kernel(const float* __restrict__ Wq,
                                                    const float* __restrict__ Wk,
                                                    const float* __restrict__ Wv,
                                                    const float* __restrict__ Wo) {
    __shared__ float t[32][33];
    const float* W = blockIdx.z == 0 ? Wq : blockIdx.z == 1 ? Wk : blockIdx.z == 2 ? Wv : Wo;
    const int bx = blockIdx.x, by = blockIdx.y;
    const int tx = threadIdx.x, ty = threadIdx.y;    // 32 x 8
    #pragma unroll
    for (int i = 0; i < 4; i++)
        t[ty + 8 * i][tx] = W[(size_t)(by * 32 + ty + 8 * i) * DIM + bx * 32 + tx];
    __syncthreads();
    size_t mbase = (size_t)blockIdx.z * DIN * DIM;
    #pragma unroll
    for (int i = 0; i < 4; i++) {
        int n = bx * 32 + ty + 8 * i;
        int k = by * 32 + tx;
        g_wt[mbase + (size_t)n * DIN + k] = __float2half(t[tx][ty + 8 * i]);
    }
}

// ======================= fp16 2-product GEMM (R5 shape, 3 smem tiles) ============
// C = (Ahi+Alo) @ W   CTA tile 128x128, k-chunk 64, 8 warps (32x64), 2 CTAs/SM.
#define GLDS 72
#define G_TILE_B (128 * GLDS * 2)      // 18432 B per tile
#define G_SMEM_TOT (3 * G_TILE_B)      // 55296 B -> 2 CTAs/SM

// EPI 0: write fp16 hi/lo pairs (per-mat).  EPI 1: write fp32 + bias.
template<int EPI>
__global__ void __launch_bounds__(256, 2)
gemm_mma(const __half* __restrict__ Ahi, const __half* __restrict__ Alo,
         const __half* __restrict__ Wt,
         __half* h0, __half* l0, __half* h1, __half* l1,
         __half* h2, __half* l2, float* fout, const float* __restrict__ bias) {
    extern __shared__ char smem[];
    const uint32_t sb = smem_u32(smem);
    const int tid  = threadIdx.x;
    const int wid  = tid >> 5;
    const int lane = tid & 31;
    const int mwarp = wid & 3;           // warp m offset = mwarp*32
    const int nwarp = wid >> 2;          // warp n offset = nwarp*64
    const int nBase = blockIdx.x * 128;
    const int mBase = blockIdx.y * 128;
    const int mat = blockIdx.z;
    const int lrow = lane & 15;
    const int lcol = (lane >> 4) * 8;

    // anti-phase chunk order for co-resident wave partners
    const int bid = blockIdx.x + gridDim.x * (blockIdx.y + gridDim.y * blockIdx.z);
    const int cph = ((bid / 148) & 1) * 4;

    __half* ohi = (mat == 0) ? h0 : (mat == 1) ? h1 : h2;
    __half* olo = (mat == 0) ? l0 : (mat == 1) ? l1 : l2;

    const __half* gsrc[3] = {
        Ahi + (size_t)mBase * DIN,
        Alo + (size_t)mBase * DIN,
        Wt + (size_t)mat * DIN * DIM + (size_t)nBase * DIN };

    float acc[2][8][4];
    #pragma unroll
    for (int a = 0; a < 2; a++)
        #pragma unroll
        for (int b = 0; b < 8; b++)
            #pragma unroll
            for (int c = 0; c < 4; c++) acc[a][b][c] = 0.f;

    for (int ci = 0; ci < 8; ci++) {
        const int kb = ((ci + cph) & 7) * 64;
        #pragma unroll
        for (int t = 0; t < 3; t++) {
            const __half* gp = gsrc[t] + kb;
            char* sp = smem + t * G_TILE_B;
            #pragma unroll
            for (int r = 0; r < 4; r++) {
                int idx = tid + r * 256;          // 0..1023
                int row = idx >> 3;               // 0..127
                int j   = idx & 7;                // 16B units (8 fp16)
                uint4 v = *(const uint4*)(gp + (size_t)row * DIN + j * 8);
                *(uint4*)(sp + row * (GLDS * 2) + j * 16) = v;
            }
        }
        __syncthreads();

        #pragma unroll
        for (int ks = 0; ks < 4; ks++) {
            const int kk = ks * 16 + lcol;
            uint32_t ah[2][4], al[2][4];
            #pragma unroll
            for (int mt = 0; mt < 2; mt++) {
                uint32_t off = (uint32_t)((mwarp * 32 + mt * 16 + lrow) * GLDS + kk) * 2;
                ldsm4(ah[mt], sb + off);
                ldsm4(al[mt], sb + G_TILE_B + off);
            }
            #pragma unroll
            for (int nb = 0; nb < 4; nb++) {
                uint32_t off = (uint32_t)((nwarp * 64 + nb * 16 + lrow) * GLDS + kk) * 2;
                uint32_t wv[4];
                ldsm4(wv, sb + 2 * G_TILE_B + off);
                #pragma unroll
                for (int mt = 0; mt < 2; mt++) {
                    float* c0 = acc[mt][2 * nb];
                    float* c1 = acc[mt][2 * nb + 1];
                    mma16816(c0, ah[mt], wv[0], wv[2]);
                    mma16816(c0, al[mt], wv[0], wv[2]);
                    mma16816(c1, ah[mt], wv[1], wv[3]);
                    mma16816(c1, al[mt], wv[1], wv[3]);
                }
            }
        }
        __syncthreads();
    }

    const int erow = lane >> 2;
    const int ecol = (lane & 3) * 2;
    #pragma unroll
    for (int mt = 0; mt < 2; mt++) {
        int r0 = mBase + mwarp * 32 + mt * 16 + erow;
        #pragma unroll
        for (int n8 = 0; n8 < 8; n8++) {
            int col = nBase + nwarp * 64 + n8 * 8 + ecol;
            float c0 = acc[mt][n8][0], c1 = acc[mt][n8][1];
            float c2 = acc[mt][n8][2], c3 = acc[mt][n8][3];
            if (EPI == 1) {
                float2 bb = *(const float2*)&bias[col];
                *(float2*)&fout[(size_t)r0 * DIM + col]       = make_float2(c0 + bb.x, c1 + bb.y);
                *(float2*)&fout[(size_t)(r0 + 8) * DIM + col] = make_float2(c2 + bb.x, c3 + bb.y);
            } else {
                uint32_t p0 = packhi(c0, c1), p1 = packhi(c2, c3);
                *(uint32_t*)&ohi[(size_t)r0 * DIM + col]       = p0;
                *(uint32_t*)&olo[(size_t)r0 * DIM + col]       = packlo(c0, c1, p0);
                *(uint32_t*)&ohi[(size_t)(r0 + 8) * DIM + col] = p1;
                *(uint32_t*)&olo[(size_t)(r0 + 8) * DIM + col] = packlo(c2, c3, p1);
            }
        }
    }
}

// ======================= tensor-core flash attention (fp16 dtype swap) ===========
#define AP 72
#define AT_B (64 * AP * 2)                 // 9216
#define A_SMEM (2 * AT_B + 2 * 4 * AT_B)   // 92160

__global__ void __launch_bounds__(128)
attn_kernel(const __half* __restrict__ qhi, const __half* __restrict__ qlo,
            const __half* __restrict__ khi, const __half* __restrict__ klo,
            const __half* __restrict__ vhi, const __half* __restrict__ vlo,
            __half* __restrict__ ohi, __half* __restrict__ olo) {
    extern __shared__ char smem[];
    const uint32_t sb = smem_u32(smem);
    const int qt = blockIdx.x, h = blockIdx.y, b = blockIdx.z;
    const int s0 = g_starts[b];
    const int ng = g_starts[b + 1] - s0;
    const int q0 = qt * 64;
    if (q0 >= ng) return;
    const int tid = threadIdx.x;
    const int w = tid >> 5, lane = tid & 31;
    const int lrow = lane & 15, lcol = (lane >> 4) * 8;

    const uint32_t sQhi = sb, sQlo = sb + AT_B;

    {
        const size_t gb = (size_t)(s0 + q0) * DIM + h * DHEAD;
        #pragma unroll
        for (int r = 0; r < 4; r++) {
            int idx = tid + r * 128;
            int m = idx >> 3, j = idx & 7;
            bool p = (q0 + m) < ng;
            uint32_t so = (uint32_t)(m * AP + j * 8) * 2;
            cpa16z(sQhi + so, qhi + gb + (size_t)m * DIM + j * 8, p);
            cpa16z(sQlo + so, qlo + gb + (size_t)m * DIM + j * 8, p);
        }
    }

    const __half* kvsrc[4] = { khi, klo, vhi, vlo };
    auto load_kv = [&](int st, int kb) {
        uint32_t sbase = sb + 2 * AT_B + st * 4 * AT_B;
        const size_t gb = (size_t)(s0 + kb) * DIM + h * DHEAD;
        #pragma unroll
        for (int t = 0; t < 4; t++)
            #pragma unroll
            for (int r = 0; r < 4; r++) {
                int idx = tid + r * 128;
                int m = idx >> 3, j = idx & 7;
                bool p = (kb + m) < ng;
                cpa16z(sbase + t * AT_B + (uint32_t)(m * AP + j * 8) * 2,
                       kvsrc[t] + gb + (size_t)m * DIM + j * 8, p);
            }
    };

    load_kv(0, 0); CP_COMMIT();

    float sv[8][4], ov[8][4];
    #pragma unroll
    for (int j = 0; j < 8; j++)
        #pragma unroll
        for (int c = 0; c < 4; c++) ov[j][c] = 0.f;
    float rm0 = -1e30f, rm1 = -1e30f, rl0 = 0.f, rl1 = 0.f;

    const int nchunks = (ng + 63) >> 6;
    for (int c = 0; c < nchunks; c++) {
        if (c + 1 < nchunks) { load_kv((c + 1) & 1, (c + 1) * 64); CP_COMMIT(); CP_WAIT(1); }
        else                 { CP_WAIT(0); }
        __syncthreads();
        const uint32_t sK  = sb + 2 * AT_B + (c & 1) * 4 * AT_B;
        const uint32_t sKl = sK + AT_B, sVh = sK + 2 * AT_B, sVl = sK + 3 * AT_B;

        #pragma unroll
        for (int j = 0; j < 8; j++)
            #pragma unroll
            for (int cc = 0; cc < 4; cc++) sv[j][cc] = 0.f;
        #pragma unroll
        for (int ks = 0; ks < 4; ks++) {
            const int kk = ks * 16 + lcol;
            uint32_t qh[4], ql[4];
            uint32_t qoff = (uint32_t)((w * 16 + lrow) * AP + kk) * 2;
            ldsm4(qh, sQhi + qoff);
            ldsm4(ql, sQlo + qoff);
            #pragma unroll
            for (int n16 = 0; n16 < 4; n16++) {
                uint32_t off = (uint32_t)((n16 * 16 + lrow) * AP + kk) * 2;
                uint32_t kh[4], kl[4];
                ldsm4(kh, sK + off);
                ldsm4(kl, sKl + off);
                float* c0 = sv[2 * n16];
                float* c1 = sv[2 * n16 + 1];
                mma16816(c0, qh, kh[0], kh[2]);
                mma16816(c0, qh, kl[0], kl[2]);
                mma16816(c0, ql, kh[0], kh[2]);
                mma16816(c1, qh, kh[1], kh[3]);
                mma16816(c1, qh, kl[1], kl[3]);
                mma16816(c1, ql, kh[1], kh[3]);
            }
        }

        const int kb = c * 64;
        #pragma unroll
        for (int j = 0; j < 8; j++) {
            int col = kb + j * 8 + (lane & 3) * 2;
            bool v0 = col < ng, v1 = (col + 1) < ng;
            sv[j][0] = v0 ? sv[j][0] * 0.125f : -1e30f;
            sv[j][1] = v1 ? sv[j][1] * 0.125f : -1e30f;
            sv[j][2] = v0 ? sv[j][2] * 0.125f : -1e30f;
            sv[j][3] = v1 ? sv[j][3] * 0.125f : -1e30f;
        }
        float m0 = -1e30f, m1 = -1e30f;
        #pragma unroll
        for (int j = 0; j < 8; j++) {
            m0 = fmaxf(m0, fmaxf(sv[j][0], sv[j][1]));
            m1 = fmaxf(m1, fmaxf(sv[j][2], sv[j][3]));
        }
        m0 = fmaxf(m0, __shfl_xor_sync(0xffffffffu, m0, 1));
        m0 = fmaxf(m0, __shfl_xor_sync(0xffffffffu, m0, 2));
        m1 = fmaxf(m1, __shfl_xor_sync(0xffffffffu, m1, 1));
        m1 = fmaxf(m1, __shfl_xor_sync(0xffffffffu, m1, 2));
        float nm0 = fmaxf(rm0, m0), nm1 = fmaxf(rm1, m1);
        float sc0 = __expf(rm0 - nm0), sc1 = __expf(rm1 - nm1);
        rm0 = nm0; rm1 = nm1;
        float l0 = 0.f, l1 = 0.f;
        #pragma unroll
        for (int j = 0; j < 8; j++) {
            sv[j][0] = __expf(sv[j][0] - nm0); l0 += sv[j][0];
            sv[j][1] = __expf(sv[j][1] - nm0); l0 += sv[j][1];
            sv[j][2] = __expf(sv[j][2] - nm1); l1 += sv[j][2];
            sv[j][3] = __expf(sv[j][3] - nm1); l1 += sv[j][3];
        }
        l0 += __shfl_xor_sync(0xffffffffu, l0, 1);
        l0 += __shfl_xor_sync(0xffffffffu, l0, 2);
        l1 += __shfl_xor_sync(0xffffffffu, l1, 1);
        l1 += __shfl_xor_sync(0xffffffffu, l1, 2);
        rl0 = rl0 * sc0 + l0;
        rl1 = rl1 * sc1 + l1;
        #pragma unroll
        for (int j = 0; j < 8; j++) {
            ov[j][0] *= sc0; ov[j][1] *= sc0;
            ov[j][2] *= sc1; ov[j][3] *= sc1;
        }

        #pragma unroll
        for (int ks = 0; ks < 4; ks++) {
            uint32_t ahi[4], alo[4];
            ahi[0] = packhi(sv[2 * ks][0], sv[2 * ks][1]);
            alo[0] = packlo(sv[2 * ks][0], sv[2 * ks][1], ahi[0]);
            ahi[1] = packhi(sv[2 * ks][2], sv[2 * ks][3]);
            alo[1] = packlo(sv[2 * ks][2], sv[2 * ks][3], ahi[1]);
            ahi[2] = packhi(sv[2 * ks + 1][0], sv[2 * ks + 1][1]);
            alo[2] = packlo(sv[2 * ks + 1][0], sv[2 * ks + 1][1], ahi[2]);
            ahi[3] = packhi(sv[2 * ks + 1][2], sv[2 * ks + 1][3]);
            alo[3] = packlo(sv[2 * ks + 1][2], sv[2 * ks + 1][3], ahi[3]);
            #pragma unroll
            for (int d16 = 0; d16 < 4; d16++) {
                uint32_t off = (uint32_t)((ks * 16 + lrow) * AP + d16 * 16 + lcol) * 2;
                uint32_t vh[4], vl[4];
                ldsm4t(vh, sVh + off);
                ldsm4t(vl, sVl + off);
                float* c0 = ov[2 * d16];
                float* c1 = ov[2 * d16 + 1];
                mma16816(c0, ahi, vh[0], vh[1]);
                mma16816(c0, ahi, vl[0], vl[1]);
                mma16816(c0, alo, vh[0], vh[1]);
                mma16816(c1, ahi, vh[2], vh[3]);
                mma16816(c1, ahi, vl[2], vl[3]);
                mma16816(c1, alo, vh[2], vh[3]);
            }
        }
        __syncthreads();
    }

    const float inv0 = 1.f / rl0, inv1 = 1.f / rl1;
    const int m0r = q0 + w * 16 + (lane >> 2);
    const bool v0 = m0r < ng, v1 = (m0r + 8) < ng;
    const size_t rb0 = (size_t)(s0 + m0r) * DIM + h * DHEAD;
    const size_t rb1 = rb0 + 8 * DIM;
    #pragma unroll
    for (int j = 0; j < 8; j++) {
        int d = j * 8 + (lane & 3) * 2;
        if (v0) {
            float x = ov[j][0] * inv0, y = ov[j][1] * inv0;
            uint32_t p = packhi(x, y);
            *(uint32_t*)&ohi[rb0 + d] = p;
            *(uint32_t*)&olo[rb0 + d] = packlo(x, y, p);
        }
        if (v1) {
            float x = ov[j][2] * inv1, y = ov[j][3] * inv1;
            uint32_t p = packhi(x, y);
            *(uint32_t*)&ohi[rb1 + d] = p;
            *(uint32_t*)&olo[rb1 + d] = packlo(x, y, p);
        }
    }
}

// ======================= launch ==================================================
extern "C" void kernel_launch(void* const* d_in, const int* in_sizes, int n_in,
                              void* d_out, int out_size) {
    const float* z     = (const float*)d_in[0];
    const int*   src   = (const int*)  d_in[1];
    const float* gamma = (const float*)d_in[2];
    const float* beta  = (const float*)d_in[3];
    const float* Wq    = (const float*)d_in[4];
    const float* Wk    = (const float*)d_in[5];
    const float* Wv    = (const float*)d_in[6];
    const float* Wo    = (const float*)d_in[7];
    const float* bo    = (const float*)d_in[8];
    float* out = (float*)d_out;

    cudaFuncSetAttribute(attn_kernel, cudaFuncAttributeMaxDynamicSharedMemorySize, A_SMEM);
    cudaFuncSetAttribute(gemm_mma<0>, cudaFuncAttributeMaxDynamicSharedMemorySize, G_SMEM_TOT);
    cudaFuncSetAttribute(gemm_mma<1>, cudaFuncAttributeMaxDynamicSharedMemorySize, G_SMEM_TOT);

    __half *ahi_p, *alo_p, *wt_p;
    __half *qh, *ql, *kh, *kl, *vh, *vl;
    cudaGetSymbolAddress((void**)&ahi_p, g_ahi);
    cudaGetSymbolAddress((void**)&alo_p, g_alo);
    cudaGetSymbolAddress((void**)&wt_p,  g_wt);
    cudaGetSymbolAddress((void**)&qh, g_qhi);
    cudaGetSymbolAddress((void**)&ql, g_qlo);
    cudaGetSymbolAddress((void**)&kh, g_khi);
    cudaGetSymbolAddress((void**)&kl, g_klo);
    cudaGetSymbolAddress((void**)&vh, g_vhi);
    cudaGetSymbolAddress((void**)&vl, g_vlo);

    starts_kernel<<<1, 64>>>(src);
    ln_kernel<<<NTOT, 128>>>(z, gamma, beta);
    wconv_kernel<<<dim3(16, 16, 4), dim3(32, 8)>>>(Wq, Wk, Wv, Wo);

    // fused Q/K/V projections -> fp16 hi/lo outputs (2-product fp16)
    gemm_mma<0><<<dim3(4, 96, 3), 256, G_SMEM_TOT>>>(
        ahi_p, alo_p, wt_p, qh, ql, kh, kl, vh, vl, nullptr, nullptr);

    attn_kernel<<<dim3(8, HEADS, NBATCH), 128, A_SMEM>>>(qh, ql, kh, kl, vh, vl, ahi_p, alo_p);

    // output projection (fp32 + bias)
    gemm_mma<1><<<dim3(4, 96, 1), 256, G_SMEM_TOT>>>(
        ahi_p, alo_p, wt_p + 3 * DIN * DIM,
        nullptr, nullptr, nullptr, nullptr, nullptr, nullptr, out, bo);
}

// round 13
// speedup vs baseline: 1.9658x; 1.2831x over previous
#include <cuda_runtime.h>
#include <cuda_fp16.h>
#include <cstdint>

#define NTOT   12288
#define DIN    512
#define DIM    512
#define HEADS  8
#define DHEAD  64
#define NBATCH 32

// ======================= PTX helpers (sm_80 ISA, valid at compute_103) ==========
__device__ __forceinline__ uint32_t smem_u32(const void* p) {
    uint32_t a;
    asm("{ .reg .u64 t; cvta.to.shared.u64 t, %1; cvt.u32.u64 %0, t; }" : "=r"(a) : "l"(p));
    return a;
}
__device__ __forceinline__ void ldsm4(uint32_t* r, uint32_t addr) {
    asm volatile("ldmatrix.sync.aligned.m8n8.x4.shared.b16 {%0,%1,%2,%3}, [%4];"
        : "=r"(r[0]), "=r"(r[1]), "=r"(r[2]), "=r"(r[3]) : "r"(addr));
}
__device__ __forceinline__ void ldsm4t(uint32_t* r, uint32_t addr) {
    asm volatile("ldmatrix.sync.aligned.m8n8.x4.trans.shared.b16 {%0,%1,%2,%3}, [%4];"
        : "=r"(r[0]), "=r"(r[1]), "=r"(r[2]), "=r"(r[3]) : "r"(addr));
}
// fp16 MMA: products exact in fp32 accumulate (11x11 mantissa bits)
__device__ __forceinline__ void mma16816(float* c, const uint32_t* a,
                                         uint32_t b0, uint32_t b1) {
    asm volatile("mma.sync.aligned.m16n8k16.row.col.f32.f16.f16.f32 "
        "{%0,%1,%2,%3}, {%4,%5,%6,%7}, {%8,%9}, {%0,%1,%2,%3};"
        : "+f"(c[0]), "+f"(c[1]), "+f"(c[2]), "+f"(c[3])
        : "r"(a[0]), "r"(a[1]), "r"(a[2]), "r"(a[3]), "r"(b0), "r"(b1));
}
__device__ __forceinline__ void cpa16z(uint32_t s, const void* g, bool p) {
    int sz = p ? 16 : 0;
    asm volatile("cp.async.cg.shared.global [%0], [%1], 16, %2;" :: "r"(s), "l"(g), "r"(sz));
}
#define CP_COMMIT() asm volatile("cp.async.commit_group;" ::: "memory")
#define CP_WAIT(n)  asm volatile("cp.async.wait_group %0;" :: "n"(n) : "memory")

__device__ __forceinline__ uint32_t packhi(float x, float y) {
    __half2 h = __floats2half2_rn(x, y);
    return *(uint32_t*)&h;
}
__device__ __forceinline__ uint32_t packlo(float x, float y, uint32_t hi) {
    __half2 h = *(__half2*)&hi;
    __half2 l = __floats2half2_rn(x - __half2float(h.x), y - __half2float(h.y));
    return *(uint32_t*)&l;
}

// ======================= scratch =================================================
__device__ __half g_a  [NTOT * DIN];      // LN output / attention output (fp16 hi)
__device__ __half g_wt [4 * DIN * DIM];   // [mat][n][k], single fp16
__device__ __half g_qhi[NTOT * DIM];
__device__ __half g_qlo[NTOT * DIM];
__device__ __half g_khi[NTOT * DIM];
__device__ __half g_klo[NTOT * DIM];
__device__ __half g_vhi[NTOT * DIM];
__device__ __half g_vlo[NTOT * DIM];
__device__ int g_starts[NBATCH + 1];

// ======================= starts ==================================================
__global__ void starts_kernel(const int* __restrict__ src) {
    int b = threadIdx.x;
    if (b > NBATCH) return;
    int lo = 0, hi = NTOT;
    while (lo < hi) { int mid = (lo + hi) >> 1; if (src[mid] < b) lo = mid + 1; else hi = mid; }
    g_starts[b] = lo;
}

// ======================= LayerNorm -> fp16 =======================================
__global__ void __launch_bounds__(128) ln_kernel(const float* __restrict__ z,
                                                 const float* __restrict__ gamma,
                                                 const float* __restrict__ beta) {
    __shared__ float red[8];
    const int row = blockIdx.x;
    const int t = threadIdx.x;
    float4 v = ((const float4*)(z + (size_t)row * DIN))[t];
    float s  = v.x + v.y + v.z + v.w;
    float ss = v.x*v.x + v.y*v.y + v.z*v.z + v.w*v.w;
    #pragma unroll
    for (int off = 16; off; off >>= 1) {
        s  += __shfl_xor_sync(0xffffffffu, s,  off);
        ss += __shfl_xor_sync(0xffffffffu, ss, off);
    }
    const int w = t >> 5;
    if ((t & 31) == 0) { red[w] = s; red[4 + w] = ss; }
    __syncthreads();
    s  = red[0] + red[1] + red[2] + red[3];
    ss = red[4] + red[5] + red[6] + red[7];
    const float mu  = s * (1.0f / DIN);
    const float var = ss * (1.0f / DIN) - mu * mu;
    const float inv = rsqrtf(var + 1e-5f);
    float4 g  = ((const float4*)gamma)[t];
    float4 be = ((const float4*)beta)[t];
    float o[4];
    o[0] = (v.x - mu) * inv * g.x + be.x;
    o[1] = (v.y - mu) * inv * g.y + be.y;
    o[2] = (v.z - mu) * inv * g.z + be.z;
    o[3] = (v.w - mu) * inv * g.w + be.w;
    size_t base = (size_t)row * DIN + t * 4;
    *(uint32_t*)&g_a[base]     = packhi(o[0], o[1]);
    *(uint32_t*)&g_a[base + 2] = packhi(o[2], o[3]);
}

// ======================= weight transpose (single fp16) ==========================
__global__ void __launch_bounds__(256) wconv_kernel(const float* __restrict__ Wq,
                                                    const float* __restrict__ Wk,
                                                    const float* __restrict__ Wv,
                                                    const float* __restrict__ Wo) {
    __shared__ float t[32][33];
    const float* W = blockIdx.z == 0 ? Wq : blockIdx.z == 1 ? Wk : blockIdx.z == 2 ? Wv : Wo;
    const int bx = blockIdx.x, by = blockIdx.y;
    const int tx = threadIdx.x, ty = threadIdx.y;    // 32 x 8
    #pragma unroll
    for (int i = 0; i < 4; i++)
        t[ty + 8 * i][tx] = W[(size_t)(by * 32 + ty + 8 * i) * DIM + bx * 32 + tx];
    __syncthreads();
    size_t mbase = (size_t)blockIdx.z * DIN * DIM;
    #pragma unroll
    for (int i = 0; i < 4; i++) {
        int n = bx * 32 + ty + 8 * i;
        int k = by * 32 + tx;
        g_wt[mbase + (size_t)n * DIN + k] = __float2half(t[tx][ty + 8 * i]);
    }
}

// ======================= fp16 single-product GEMM (R5 shape, 2 smem tiles) =======
// C = A @ W   CTA tile 128x128, k-chunk 64, 8 warps (32x64), 2 CTAs/SM.
#define GLDS 72
#define G_TILE_B (128 * GLDS * 2)      // 18432 B per tile
#define G_SMEM_TOT (2 * G_TILE_B)      // 36864 B

// EPI 0: write fp16 hi/lo pairs (per-mat).  EPI 1: write fp32 + bias.
template<int EPI>
__global__ void __launch_bounds__(256, 2)
gemm_mma(const __half* __restrict__ A, const __half* __restrict__ Wt,
         __half* h0, __half* l0, __half* h1, __half* l1,
         __half* h2, __half* l2, float* fout, const float* __restrict__ bias) {
    extern __shared__ char smem[];
    const uint32_t sb = smem_u32(smem);
    const int tid  = threadIdx.x;
    const int wid  = tid >> 5;
    const int lane = tid & 31;
    const int mwarp = wid & 3;           // warp m offset = mwarp*32
    const int nwarp = wid >> 2;          // warp n offset = nwarp*64
    const int nBase = blockIdx.x * 128;
    const int mBase = blockIdx.y * 128;
    const int mat = blockIdx.z;
    const int lrow = lane & 15;
    const int lcol = (lane >> 4) * 8;

    // anti-phase chunk order for co-resident wave partners
    const int bid = blockIdx.x + gridDim.x * (blockIdx.y + gridDim.y * blockIdx.z);
    const int cph = ((bid / 148) & 1) * 4;

    __half* ohi = (mat == 0) ? h0 : (mat == 1) ? h1 : h2;
    __half* olo = (mat == 0) ? l0 : (mat == 1) ? l1 : l2;

    const __half* gsrc[2] = {
        A + (size_t)mBase * DIN,
        Wt + (size_t)mat * DIN * DIM + (size_t)nBase * DIN };

    float acc[2][8][4];
    #pragma unroll
    for (int a = 0; a < 2; a++)
        #pragma unroll
        for (int b = 0; b < 8; b++)
            #pragma unroll
            for (int c = 0; c < 4; c++) acc[a][b][c] = 0.f;

    for (int ci = 0; ci < 8; ci++) {
        const int kb = ((ci + cph) & 7) * 64;
        #pragma unroll
        for (int t = 0; t < 2; t++) {
            const __half* gp = gsrc[t] + kb;
            char* sp = smem + t * G_TILE_B;
            #pragma unroll
            for (int r = 0; r < 4; r++) {
                int idx = tid + r * 256;          // 0..1023
                int row = idx >> 3;               // 0..127
                int j   = idx & 7;                // 16B units (8 fp16)
                uint4 v = *(const uint4*)(gp + (size_t)row * DIN + j * 8);
                *(uint4*)(sp + row * (GLDS * 2) + j * 16) = v;
            }
        }
        __syncthreads();

        #pragma unroll
        for (int ks = 0; ks < 4; ks++) {
            const int kk = ks * 16 + lcol;
            uint32_t ah[2][4];
            #pragma unroll
            for (int mt = 0; mt < 2; mt++) {
                uint32_t off = (uint32_t)((mwarp * 32 + mt * 16 + lrow) * GLDS + kk) * 2;
                ldsm4(ah[mt], sb + off);
            }
            #pragma unroll
            for (int nb = 0; nb < 4; nb++) {
                uint32_t off = (uint32_t)((nwarp * 64 + nb * 16 + lrow) * GLDS + kk) * 2;
                uint32_t wv[4];
                ldsm4(wv, sb + G_TILE_B + off);
                #pragma unroll
                for (int mt = 0; mt < 2; mt++) {
                    mma16816(acc[mt][2 * nb],     ah[mt], wv[0], wv[2]);
                    mma16816(acc[mt][2 * nb + 1], ah[mt], wv[1], wv[3]);
                }
            }
        }
        __syncthreads();
    }

    const int erow = lane >> 2;
    const int ecol = (lane & 3) * 2;
    #pragma unroll
    for (int mt = 0; mt < 2; mt++) {
        int r0 = mBase + mwarp * 32 + mt * 16 + erow;
        #pragma unroll
        for (int n8 = 0; n8 < 8; n8++) {
            int col = nBase + nwarp * 64 + n8 * 8 + ecol;
            float c0 = acc[mt][n8][0], c1 = acc[mt][n8][1];
            float c2 = acc[mt][n8][2], c3 = acc[mt][n8][3];
            if (EPI == 1) {
                float2 bb = *(const float2*)&bias[col];
                *(float2*)&fout[(size_t)r0 * DIM + col]       = make_float2(c0 + bb.x, c1 + bb.y);
                *(float2*)&fout[(size_t)(r0 + 8) * DIM + col] = make_float2(c2 + bb.x, c3 + bb.y);
            } else {
                uint32_t p0 = packhi(c0, c1), p1 = packhi(c2, c3);
                *(uint32_t*)&ohi[(size_t)r0 * DIM + col]       = p0;
                *(uint32_t*)&olo[(size_t)r0 * DIM + col]       = packlo(c0, c1, p0);
                *(uint32_t*)&ohi[(size_t)(r0 + 8) * DIM + col] = p1;
                *(uint32_t*)&olo[(size_t)(r0 + 8) * DIM + col] = packlo(c2, c3, p1);
            }
        }
    }
}

// ======================= tensor-core flash attention (3-product, fp16) ===========
#define AP 72
#define AT_B (64 * AP * 2)                 // 9216
#define A_SMEM (2 * AT_B + 2 * 4 * AT_B)   // 92160

__global__ void __launch_bounds__(128)
attn_kernel(const __half* __restrict__ qhi, const __half* __restrict__ qlo,
            const __half* __restrict__ khi, const __half* __restrict__ klo,
            const __half* __restrict__ vhi, const __half* __restrict__ vlo,
            __half* __restrict__ oout) {
    extern __shared__ char smem[];
    const uint32_t sb = smem_u32(smem);
    const int qt = blockIdx.x, h = blockIdx.y, b = blockIdx.z;
    const int s0 = g_starts[b];
    const int ng = g_starts[b + 1] - s0;
    const int q0 = qt * 64;
    if (q0 >= ng) return;
    const int tid = threadIdx.x;
    const int w = tid >> 5, lane = tid & 31;
    const int lrow = lane & 15, lcol = (lane >> 4) * 8;

    const uint32_t sQhi = sb, sQlo = sb + AT_B;

    {
        const size_t gb = (size_t)(s0 + q0) * DIM + h * DHEAD;
        #pragma unroll
        for (int r = 0; r < 4; r++) {
            int idx = tid + r * 128;
            int m = idx >> 3, j = idx & 7;
            bool p = (q0 + m) < ng;
            uint32_t so = (uint32_t)(m * AP + j * 8) * 2;
            cpa16z(sQhi + so, qhi + gb + (size_t)m * DIM + j * 8, p);
            cpa16z(sQlo + so, qlo + gb + (size_t)m * DIM + j * 8, p);
        }
    }

    const __half* kvsrc[4] = { khi, klo, vhi, vlo };
    auto load_kv = [&](int st, int kb) {
        uint32_t sbase = sb + 2 * AT_B + st * 4 * AT_B;
        const size_t gb = (size_t)(s0 + kb) * DIM + h * DHEAD;
        #pragma unroll
        for (int t = 0; t < 4; t++)
            #pragma unroll
            for (int r = 0; r < 4; r++) {
                int idx = tid + r * 128;
                int m = idx >> 3, j = idx & 7;
                bool p = (kb + m) < ng;
                cpa16z(sbase + t * AT_B + (uint32_t)(m * AP + j * 8) * 2,
                       kvsrc[t] + gb + (size_t)m * DIM + j * 8, p);
            }
    };

    load_kv(0, 0); CP_COMMIT();

    float sv[8][4], ov[8][4];
    #pragma unroll
    for (int j = 0; j < 8; j++)
        #pragma unroll
        for (int c = 0; c < 4; c++) ov[j][c] = 0.f;
    float rm0 = -1e30f, rm1 = -1e30f, rl0 = 0.f, rl1 = 0.f;

    const int nchunks = (ng + 63) >> 6;
    for (int c = 0; c < nchunks; c++) {
        if (c + 1 < nchunks) { load_kv((c + 1) & 1, (c + 1) * 64); CP_COMMIT(); CP_WAIT(1); }
        else                 { CP_WAIT(0); }
        __syncthreads();
        const uint32_t sK  = sb + 2 * AT_B + (c & 1) * 4 * AT_B;
        const uint32_t sKl = sK + AT_B, sVh = sK + 2 * AT_B, sVl = sK + 3 * AT_B;

        #pragma unroll
        for (int j = 0; j < 8; j++)
            #pragma unroll
            for (int cc = 0; cc < 4; cc++) sv[j][cc] = 0.f;
        #pragma unroll
        for (int ks = 0; ks < 4; ks++) {
            const int kk = ks * 16 + lcol;
            uint32_t qh[4], ql[4];
            uint32_t qoff = (uint32_t)((w * 16 + lrow) * AP + kk) * 2;
            ldsm4(qh, sQhi + qoff);
            ldsm4(ql, sQlo + qoff);
            #pragma unroll
            for (int n16 = 0; n16 < 4; n16++) {
                uint32_t off = (uint32_t)((n16 * 16 + lrow) * AP + kk) * 2;
                uint32_t kh[4], kl[4];
                ldsm4(kh, sK + off);
                ldsm4(kl, sKl + off);
                float* c0 = sv[2 * n16];
                float* c1 = sv[2 * n16 + 1];
                mma16816(c0, qh, kh[0], kh[2]);
                mma16816(c0, qh, kl[0], kl[2]);
                mma16816(c0, ql, kh[0], kh[2]);
                mma16816(c1, qh, kh[1], kh[3]);
                mma16816(c1, qh, kl[1], kl[3]);
                mma16816(c1, ql, kh[1], kh[3]);
            }
        }

        const int kb = c * 64;
        #pragma unroll
        for (int j = 0; j < 8; j++) {
            int col = kb + j * 8 + (lane & 3) * 2;
            bool v0 = col < ng, v1 = (col + 1) < ng;
            sv[j][0] = v0 ? sv[j][0] * 0.125f : -1e30f;
            sv[j][1] = v1 ? sv[j][1] * 0.125f : -1e30f;
            sv[j][2] = v0 ? sv[j][2] * 0.125f : -1e30f;
            sv[j][3] = v1 ? sv[j][3] * 0.125f : -1e30f;
        }
        float m0 = -1e30f, m1 = -1e30f;
        #pragma unroll
        for (int j = 0; j < 8; j++) {
            m0 = fmaxf(m0, fmaxf(sv[j][0], sv[j][1]));
            m1 = fmaxf(m1, fmaxf(sv[j][2], sv[j][3]));
        }
        m0 = fmaxf(m0, __shfl_xor_sync(0xffffffffu, m0, 1));
        m0 = fmaxf(m0, __shfl_xor_sync(0xffffffffu, m0, 2));
        m1 = fmaxf(m1, __shfl_xor_sync(0xffffffffu, m1, 1));
        m1 = fmaxf(m1, __shfl_xor_sync(0xffffffffu, m1, 2));
        float nm0 = fmaxf(rm0, m0), nm1 = fmaxf(rm1, m1);
        float sc0 = __expf(rm0 - nm0), sc1 = __expf(rm1 - nm1);
        rm0 = nm0; rm1 = nm1;
        float l0 = 0.f, l1 = 0.f;
        #pragma unroll
        for (int j = 0; j < 8; j++) {
            sv[j][0] = __expf(sv[j][0] - nm0); l0 += sv[j][0];
            sv[j][1] = __expf(sv[j][1] - nm0); l0 += sv[j][1];
            sv[j][2] = __expf(sv[j][2] - nm1); l1 += sv[j][2];
            sv[j][3] = __expf(sv[j][3] - nm1); l1 += sv[j][3];
        }
        l0 += __shfl_xor_sync(0xffffffffu, l0, 1);
        l0 += __shfl_xor_sync(0xffffffffu, l0, 2);
        l1 += __shfl_xor_sync(0xffffffffu, l1, 1);
        l1 += __shfl_xor_sync(0xffffffffu, l1, 2);
        rl0 = rl0 * sc0 + l0;
        rl1 = rl1 * sc1 + l1;
        #pragma unroll
        for (int j = 0; j < 8; j++) {
            ov[j][0] *= sc0; ov[j][1] *= sc0;
            ov[j][2] *= sc1; ov[j][3] *= sc1;
        }

        #pragma unroll
        for (int ks = 0; ks < 4; ks++) {
            uint32_t ahi[4], alo[4];
            ahi[0] = packhi(sv[2 * ks][0], sv[2 * ks][1]);
            alo[0] = packlo(sv[2 * ks][0], sv[2 * ks][1], ahi[0]);
            ahi[1] = packhi(sv[2 * ks][2], sv[2 * ks][3]);
            alo[1] = packlo(sv[2 * ks][2], sv[2 * ks][3], ahi[1]);
            ahi[2] = packhi(sv[2 * ks + 1][0], sv[2 * ks + 1][1]);
            alo[2] = packlo(sv[2 * ks + 1][0], sv[2 * ks + 1][1], ahi[2]);
            ahi[3] = packhi(sv[2 * ks + 1][2], sv[2 * ks + 1][3]);
            alo[3] = packlo(sv[2 * ks + 1][2], sv[2 * ks + 1][3], ahi[3]);
            #pragma unroll
            for (int d16 = 0; d16 < 4; d16++) {
                uint32_t off = (uint32_t)((ks * 16 + lrow) * AP + d16 * 16 + lcol) * 2;
                uint32_t vh[4], vl[4];
                ldsm4t(vh, sVh + off);
                ldsm4t(vl, sVl + off);
                float* c0 = ov[2 * d16];
                float* c1 = ov[2 * d16 + 1];
                mma16816(c0, ahi, vh[0], vh[1]);
                mma16816(c0, ahi, vl[0], vl[1]);
                mma16816(c0, alo, vh[0], vh[1]);
                mma16816(c1, ahi, vh[2], vh[3]);
                mma16816(c1, ahi, vl[2], vl[3]);
                mma16816(c1, alo, vh[2], vh[3]);
            }
        }
        __syncthreads();
    }

    // epilogue: normalize, write fp16 (single) for the Wo GEMM
    const float inv0 = 1.f / rl0, inv1 = 1.f / rl1;
    const int m0r = q0 + w * 16 + (lane >> 2);
    const bool v0 = m0r < ng, v1 = (m0r + 8) < ng;
    const size_t rb0 = (size_t)(s0 + m0r) * DIM + h * DHEAD;
    const size_t rb1 = rb0 + 8 * DIM;
    #pragma unroll
    for (int j = 0; j < 8; j++) {
        int d = j * 8 + (lane & 3) * 2;
        if (v0)
            *(uint32_t*)&oout[rb0 + d] = packhi(ov[j][0] * inv0, ov[j][1] * inv0);
        if (v1)
            *(uint32_t*)&oout[rb1 + d] = packhi(ov[j][2] * inv1, ov[j][3] * inv1);
    }
}

// ======================= launch ==================================================
extern "C" void kernel_launch(void* const* d_in, const int* in_sizes, int n_in,
                              void* d_out, int out_size) {
    const float* z     = (const float*)d_in[0];
    const int*   src   = (const int*)  d_in[1];
    const float* gamma = (const float*)d_in[2];
    const float* beta  = (const float*)d_in[3];
    const float* Wq    = (const float*)d_in[4];
    const float* Wk    = (const float*)d_in[5];
    const float* Wv    = (const float*)d_in[6];
    const float* Wo    = (const float*)d_in[7];
    const float* bo    = (const float*)d_in[8];
    float* out = (float*)d_out;

    cudaFuncSetAttribute(attn_kernel, cudaFuncAttributeMaxDynamicSharedMemorySize, A_SMEM);
    cudaFuncSetAttribute(gemm_mma<0>, cudaFuncAttributeMaxDynamicSharedMemorySize, G_SMEM_TOT);
    cudaFuncSetAttribute(gemm_mma<1>, cudaFuncAttributeMaxDynamicSharedMemorySize, G_SMEM_TOT);

    __half *a_p, *wt_p;
    __half *qh, *ql, *kh, *kl, *vh, *vl;
    cudaGetSymbolAddress((void**)&a_p,  g_a);
    cudaGetSymbolAddress((void**)&wt_p, g_wt);
    cudaGetSymbolAddress((void**)&qh, g_qhi);
    cudaGetSymbolAddress((void**)&ql, g_qlo);
    cudaGetSymbolAddress((void**)&kh, g_khi);
    cudaGetSymbolAddress((void**)&kl, g_klo);
    cudaGetSymbolAddress((void**)&vh, g_vhi);
    cudaGetSymbolAddress((void**)&vl, g_vlo);

    starts_kernel<<<1, 64>>>(src);
    ln_kernel<<<NTOT, 128>>>(z, gamma, beta);
    wconv_kernel<<<dim3(16, 16, 4), dim3(32, 8)>>>(Wq, Wk, Wv, Wo);

    // fused Q/K/V projections (single-product fp16) -> fp16 hi/lo outputs
    gemm_mma<0><<<dim3(4, 96, 3), 256, G_SMEM_TOT>>>(
        a_p, wt_p, qh, ql, kh, kl, vh, vl, nullptr, nullptr);

    attn_kernel<<<dim3(8, HEADS, NBATCH), 128, A_SMEM>>>(qh, ql, kh, kl, vh, vl, a_p);

    // output projection (fp32 + bias)
    gemm_mma<1><<<dim3(4, 96, 1), 256, G_SMEM_TOT>>>(
        a_p, wt_p + 3 * DIN * DIM,
        nullptr, nullptr, nullptr, nullptr, nullptr, nullptr, out, bo);
}

// round 14
// speedup vs baseline: 2.7399x; 1.3938x over previous
#include <cuda_runtime.h>
#include <cuda_fp16.h>
#include <cstdint>

#define NTOT   12288
#define DIN    512
#define DIM    512
#define HEADS  8
#define DHEAD  64
#define NBATCH 32

// ======================= PTX helpers (sm_80 ISA, valid at compute_103) ==========
__device__ __forceinline__ uint32_t smem_u32(const void* p) {
    uint32_t a;
    asm("{ .reg .u64 t; cvta.to.shared.u64 t, %1; cvt.u32.u64 %0, t; }" : "=r"(a) : "l"(p));
    return a;
}
__device__ __forceinline__ void ldsm4(uint32_t* r, uint32_t addr) {
    asm volatile("ldmatrix.sync.aligned.m8n8.x4.shared.b16 {%0,%1,%2,%3}, [%4];"
        : "=r"(r[0]), "=r"(r[1]), "=r"(r[2]), "=r"(r[3]) : "r"(addr));
}
__device__ __forceinline__ void ldsm4t(uint32_t* r, uint32_t addr) {
    asm volatile("ldmatrix.sync.aligned.m8n8.x4.trans.shared.b16 {%0,%1,%2,%3}, [%4];"
        : "=r"(r[0]), "=r"(r[1]), "=r"(r[2]), "=r"(r[3]) : "r"(addr));
}
__device__ __forceinline__ void mma16816(float* c, const uint32_t* a,
                                         uint32_t b0, uint32_t b1) {
    asm volatile("mma.sync.aligned.m16n8k16.row.col.f32.f16.f16.f32 "
        "{%0,%1,%2,%3}, {%4,%5,%6,%7}, {%8,%9}, {%0,%1,%2,%3};"
        : "+f"(c[0]), "+f"(c[1]), "+f"(c[2]), "+f"(c[3])
        : "r"(a[0]), "r"(a[1]), "r"(a[2]), "r"(a[3]), "r"(b0), "r"(b1));
}
__device__ __forceinline__ void cpa16z(uint32_t s, const void* g, bool p) {
    int sz = p ? 16 : 0;
    asm volatile("cp.async.cg.shared.global [%0], [%1], 16, %2;" :: "r"(s), "l"(g), "r"(sz));
}
#define CP_COMMIT() asm volatile("cp.async.commit_group;" ::: "memory")
#define CP_WAIT(n)  asm volatile("cp.async.wait_group %0;" :: "n"(n) : "memory")

__device__ __forceinline__ uint32_t packhi(float x, float y) {
    __half2 h = __floats2half2_rn(x, y);
    return *(uint32_t*)&h;
}

// ======================= scratch =================================================
__device__ __half g_a [NTOT * DIN];      // LN output / attention output (fp16)
__device__ __half g_wt[4 * DIN * DIM];   // [mat][n][k], single fp16
__device__ __half g_q [NTOT * DIM];
__device__ __half g_k [NTOT * DIM];
__device__ __half g_v [NTOT * DIM];
__device__ int g_starts[NBATCH + 1];

// ======================= starts ==================================================
__global__ void starts_kernel(const int* __restrict__ src) {
    int b = threadIdx.x;
    if (b > NBATCH) return;
    int lo = 0, hi = NTOT;
    while (lo < hi) { int mid = (lo + hi) >> 1; if (src[mid] < b) lo = mid + 1; else hi = mid; }
    g_starts[b] = lo;
}

// ======================= LayerNorm (warp per row) -> fp16 ========================
__global__ void __launch_bounds__(256) ln_kernel(const float* __restrict__ z,
                                                 const float* __restrict__ gamma,
                                                 const float* __restrict__ beta) {
    const int row  = blockIdx.x * 8 + (threadIdx.x >> 5);
    const int lane = threadIdx.x & 31;
    const float* zr = z + (size_t)row * DIN;
    float4 v[4];
    float s = 0.f, ss = 0.f;
    #pragma unroll
    for (int i = 0; i < 4; i++) {
        v[i] = ((const float4*)zr)[lane + i * 32];
        s  += v[i].x + v[i].y + v[i].z + v[i].w;
        ss += v[i].x*v[i].x + v[i].y*v[i].y + v[i].z*v[i].z + v[i].w*v[i].w;
    }
    #pragma unroll
    for (int off = 16; off; off >>= 1) {
        s  += __shfl_xor_sync(0xffffffffu, s,  off);
        ss += __shfl_xor_sync(0xffffffffu, ss, off);
    }
    const float mu  = s * (1.0f / DIN);
    const float var = ss * (1.0f / DIN) - mu * mu;
    const float inv = rsqrtf(var + 1e-5f);
    #pragma unroll
    for (int i = 0; i < 4; i++) {
        const int c4 = lane + i * 32;
        float4 g  = ((const float4*)gamma)[c4];
        float4 be = ((const float4*)beta)[c4];
        float o0 = (v[i].x - mu) * inv * g.x + be.x;
        float o1 = (v[i].y - mu) * inv * g.y + be.y;
        float o2 = (v[i].z - mu) * inv * g.z + be.z;
        float o3 = (v[i].w - mu) * inv * g.w + be.w;
        size_t base = (size_t)row * DIN + c4 * 4;
        *(uint32_t*)&g_a[base]     = packhi(o0, o1);
        *(uint32_t*)&g_a[base + 2] = packhi(o2, o3);
    }
}

// ======================= weight transpose (single fp16) ==========================
__global__ void __launch_bounds__(256) wconv_kernel(const float* __restrict__ Wq,
                                                    const float* __restrict__ Wk,
                                                    const float* __restrict__ Wv,
                                                    const float* __restrict__ Wo) {
    __shared__ float t[32][33];
    const float* W = blockIdx.z == 0 ? Wq : blockIdx.z == 1 ? Wk : blockIdx.z == 2 ? Wv : Wo;
    const int bx = blockIdx.x, by = blockIdx.y;
    const int tx = threadIdx.x, ty = threadIdx.y;    // 32 x 8
    #pragma unroll
    for (int i = 0; i < 4; i++)
        t[ty + 8 * i][tx] = W[(size_t)(by * 32 + ty + 8 * i) * DIM + bx * 32 + tx];
    __syncthreads();
    size_t mbase = (size_t)blockIdx.z * DIN * DIM;
    #pragma unroll
    for (int i = 0; i < 4; i++) {
        int n = bx * 32 + ty + 8 * i;
        int k = by * 32 + tx;
        g_wt[mbase + (size_t)n * DIN + k] = __float2half(t[tx][ty + 8 * i]);
    }
}

// ======================= fp16 single-product GEMM (R13 measured-good) ============
// C = A @ W   CTA tile 128x128, k-chunk 64, 8 warps (32x64), 2 CTAs/SM.
#define GLDS 72
#define G_TILE_B (128 * GLDS * 2)      // 18432 B per tile
#define G_SMEM_TOT (2 * G_TILE_B)      // 36864 B

// EPI 0: write fp16 per-mat.  EPI 1: write fp32 + bias.
template<int EPI>
__global__ void __launch_bounds__(256, 2)
gemm_mma(const __half* __restrict__ A, const __half* __restrict__ Wt,
         __half* o0, __half* o1, __half* o2,
         float* fout, const float* __restrict__ bias) {
    extern __shared__ char smem[];
    const uint32_t sb = smem_u32(smem);
    const int tid  = threadIdx.x;
    const int wid  = tid >> 5;
    const int lane = tid & 31;
    const int mwarp = wid & 3;
    const int nwarp = wid >> 2;
    const int nBase = blockIdx.x * 128;
    const int mBase = blockIdx.y * 128;
    const int mat = blockIdx.z;
    const int lrow = lane & 15;
    const int lcol = (lane >> 4) * 8;

    const int bid = blockIdx.x + gridDim.x * (blockIdx.y + gridDim.y * blockIdx.z);
    const int cph = ((bid / 148) & 1) * 4;

    __half* ohp = (mat == 0) ? o0 : (mat == 1) ? o1 : o2;

    const __half* gsrc[2] = {
        A + (size_t)mBase * DIN,
        Wt + (size_t)mat * DIN * DIM + (size_t)nBase * DIN };

    float acc[2][8][4];
    #pragma unroll
    for (int a = 0; a < 2; a++)
        #pragma unroll
        for (int b = 0; b < 8; b++)
            #pragma unroll
            for (int c = 0; c < 4; c++) acc[a][b][c] = 0.f;

    for (int ci = 0; ci < 8; ci++) {
        const int kb = ((ci + cph) & 7) * 64;
        #pragma unroll
        for (int t = 0; t < 2; t++) {
            const __half* gp = gsrc[t] + kb;
            char* sp = smem + t * G_TILE_B;
            #pragma unroll
            for (int r = 0; r < 4; r++) {
                int idx = tid + r * 256;
                int row = idx >> 3;
                int j   = idx & 7;
                uint4 v = *(const uint4*)(gp + (size_t)row * DIN + j * 8);
                *(uint4*)(sp + row * (GLDS * 2) + j * 16) = v;
            }
        }
        __syncthreads();

        #pragma unroll
        for (int ks = 0; ks < 4; ks++) {
            const int kk = ks * 16 + lcol;
            uint32_t ah[2][4];
            #pragma unroll
            for (int mt = 0; mt < 2; mt++) {
                uint32_t off = (uint32_t)((mwarp * 32 + mt * 16 + lrow) * GLDS + kk) * 2;
                ldsm4(ah[mt], sb + off);
            }
            #pragma unroll
            for (int nb = 0; nb < 4; nb++) {
                uint32_t off = (uint32_t)((nwarp * 64 + nb * 16 + lrow) * GLDS + kk) * 2;
                uint32_t wv[4];
                ldsm4(wv, sb + G_TILE_B + off);
                #pragma unroll
                for (int mt = 0; mt < 2; mt++) {
                    mma16816(acc[mt][2 * nb],     ah[mt], wv[0], wv[2]);
                    mma16816(acc[mt][2 * nb + 1], ah[mt], wv[1], wv[3]);
                }
            }
        }
        __syncthreads();
    }

    const int erow = lane >> 2;
    const int ecol = (lane & 3) * 2;
    #pragma unroll
    for (int mt = 0; mt < 2; mt++) {
        int r0 = mBase + mwarp * 32 + mt * 16 + erow;
        #pragma unroll
        for (int n8 = 0; n8 < 8; n8++) {
            int col = nBase + nwarp * 64 + n8 * 8 + ecol;
            float c0 = acc[mt][n8][0], c1 = acc[mt][n8][1];
            float c2 = acc[mt][n8][2], c3 = acc[mt][n8][3];
            if (EPI == 1) {
                float2 bb = *(const float2*)&bias[col];
                *(float2*)&fout[(size_t)r0 * DIM + col]       = make_float2(c0 + bb.x, c1 + bb.y);
                *(float2*)&fout[(size_t)(r0 + 8) * DIM + col] = make_float2(c2 + bb.x, c3 + bb.y);
            } else {
                *(uint32_t*)&ohp[(size_t)r0 * DIM + col]       = packhi(c0, c1);
                *(uint32_t*)&ohp[(size_t)(r0 + 8) * DIM + col] = packhi(c2, c3);
            }
        }
    }
}

// ======================= tensor-core flash attention (single-product fp16) =======
#define AP 72
#define AT_B (64 * AP * 2)                 // 9216
#define A_SMEM (AT_B + 2 * 2 * AT_B)       // 46080: Q + 2 stages x (K,V)

__global__ void __launch_bounds__(128)
attn_kernel(const __half* __restrict__ q, const __half* __restrict__ k,
            const __half* __restrict__ v, __half* __restrict__ oout) {
    extern __shared__ char smem[];
    const uint32_t sb = smem_u32(smem);
    const int qt = blockIdx.x, h = blockIdx.y, b = blockIdx.z;
    const int s0 = g_starts[b];
    const int ng = g_starts[b + 1] - s0;
    const int q0 = qt * 64;
    if (q0 >= ng) return;
    const int tid = threadIdx.x;
    const int w = tid >> 5, lane = tid & 31;
    const int lrow = lane & 15, lcol = (lane >> 4) * 8;

    const uint32_t sQ = sb;

    {
        const size_t gb = (size_t)(s0 + q0) * DIM + h * DHEAD;
        #pragma unroll
        for (int r = 0; r < 4; r++) {
            int idx = tid + r * 128;
            int m = idx >> 3, j = idx & 7;
            bool p = (q0 + m) < ng;
            cpa16z(sQ + (uint32_t)(m * AP + j * 8) * 2, q + gb + (size_t)m * DIM + j * 8, p);
        }
    }

    const __half* kvsrc[2] = { k, v };
    auto load_kv = [&](int st, int kb) {
        uint32_t sbase = sb + AT_B + st * 2 * AT_B;
        const size_t gb = (size_t)(s0 + kb) * DIM + h * DHEAD;
        #pragma unroll
        for (int t = 0; t < 2; t++)
            #pragma unroll
            for (int r = 0; r < 4; r++) {
                int idx = tid + r * 128;
                int m = idx >> 3, j = idx & 7;
                bool p = (kb + m) < ng;
                cpa16z(sbase + t * AT_B + (uint32_t)(m * AP + j * 8) * 2,
                       kvsrc[t] + gb + (size_t)m * DIM + j * 8, p);
            }
    };

    load_kv(0, 0); CP_COMMIT();

    float sv[8][4], ov[8][4];
    #pragma unroll
    for (int j = 0; j < 8; j++)
        #pragma unroll
        for (int c = 0; c < 4; c++) ov[j][c] = 0.f;
    float rm0 = -1e30f, rm1 = -1e30f, rl0 = 0.f, rl1 = 0.f;

    const int nchunks = (ng + 63) >> 6;
    for (int c = 0; c < nchunks; c++) {
        if (c + 1 < nchunks) { load_kv((c + 1) & 1, (c + 1) * 64); CP_COMMIT(); CP_WAIT(1); }
        else                 { CP_WAIT(0); }
        __syncthreads();
        const uint32_t sK = sb + AT_B + (c & 1) * 2 * AT_B;
        const uint32_t sV = sK + AT_B;

        // ---- S = Q K^T (single product) ----
        #pragma unroll
        for (int j = 0; j < 8; j++)
            #pragma unroll
            for (int cc = 0; cc < 4; cc++) sv[j][cc] = 0.f;
        #pragma unroll
        for (int ks = 0; ks < 4; ks++) {
            const int kk = ks * 16 + lcol;
            uint32_t qh[4];
            ldsm4(qh, sQ + (uint32_t)((w * 16 + lrow) * AP + kk) * 2);
            #pragma unroll
            for (int n16 = 0; n16 < 4; n16++) {
                uint32_t kh[4];
                ldsm4(kh, sK + (uint32_t)((n16 * 16 + lrow) * AP + kk) * 2);
                mma16816(sv[2 * n16],     qh, kh[0], kh[2]);
                mma16816(sv[2 * n16 + 1], qh, kh[1], kh[3]);
            }
        }

        // ---- online softmax ----
        const int kb = c * 64;
        #pragma unroll
        for (int j = 0; j < 8; j++) {
            int col = kb + j * 8 + (lane & 3) * 2;
            bool v0 = col < ng, v1 = (col + 1) < ng;
            sv[j][0] = v0 ? sv[j][0] * 0.125f : -1e30f;
            sv[j][1] = v1 ? sv[j][1] * 0.125f : -1e30f;
            sv[j][2] = v0 ? sv[j][2] * 0.125f : -1e30f;
            sv[j][3] = v1 ? sv[j][3] * 0.125f : -1e30f;
        }
        float m0 = -1e30f, m1 = -1e30f;
        #pragma unroll
        for (int j = 0; j < 8; j++) {
            m0 = fmaxf(m0, fmaxf(sv[j][0], sv[j][1]));
            m1 = fmaxf(m1, fmaxf(sv[j][2], sv[j][3]));
        }
        m0 = fmaxf(m0, __shfl_xor_sync(0xffffffffu, m0, 1));
        m0 = fmaxf(m0, __shfl_xor_sync(0xffffffffu, m0, 2));
        m1 = fmaxf(m1, __shfl_xor_sync(0xffffffffu, m1, 1));
        m1 = fmaxf(m1, __shfl_xor_sync(0xffffffffu, m1, 2));
        float nm0 = fmaxf(rm0, m0), nm1 = fmaxf(rm1, m1);
        float sc0 = __expf(rm0 - nm0), sc1 = __expf(rm1 - nm1);
        rm0 = nm0; rm1 = nm1;
        float l0 = 0.f, l1 = 0.f;
        #pragma unroll
        for (int j = 0; j < 8; j++) {
            sv[j][0] = __expf(sv[j][0] - nm0); l0 += sv[j][0];
            sv[j][1] = __expf(sv[j][1] - nm0); l0 += sv[j][1];
            sv[j][2] = __expf(sv[j][2] - nm1); l1 += sv[j][2];
            sv[j][3] = __expf(sv[j][3] - nm1); l1 += sv[j][3];
        }
        l0 += __shfl_xor_sync(0xffffffffu, l0, 1);
        l0 += __shfl_xor_sync(0xffffffffu, l0, 2);
        l1 += __shfl_xor_sync(0xffffffffu, l1, 1);
        l1 += __shfl_xor_sync(0xffffffffu, l1, 2);
        rl0 = rl0 * sc0 + l0;
        rl1 = rl1 * sc1 + l1;
        #pragma unroll
        for (int j = 0; j < 8; j++) {
            ov[j][0] *= sc0; ov[j][1] *= sc0;
            ov[j][2] *= sc1; ov[j][3] *= sc1;
        }

        // ---- O += P V (single product; P repacked in-register) ----
        #pragma unroll
        for (int ks = 0; ks < 4; ks++) {
            uint32_t ah[4];
            ah[0] = packhi(sv[2 * ks][0],     sv[2 * ks][1]);
            ah[1] = packhi(sv[2 * ks][2],     sv[2 * ks][3]);
            ah[2] = packhi(sv[2 * ks + 1][0], sv[2 * ks + 1][1]);
            ah[3] = packhi(sv[2 * ks + 1][2], sv[2 * ks + 1][3]);
            #pragma unroll
            for (int d16 = 0; d16 < 4; d16++) {
                uint32_t off = (uint32_t)((ks * 16 + lrow) * AP + d16 * 16 + lcol) * 2;
                uint32_t vh[4];
                ldsm4t(vh, sV + off);
                mma16816(ov[2 * d16],     ah, vh[0], vh[1]);
                mma16816(ov[2 * d16 + 1], ah, vh[2], vh[3]);
            }
        }
        __syncthreads();
    }

    // ---- epilogue: normalize, write fp16 for the Wo GEMM ----
    const float inv0 = 1.f / rl0, inv1 = 1.f / rl1;
    const int m0r = q0 + w * 16 + (lane >> 2);
    const bool v0 = m0r < ng, v1 = (m0r + 8) < ng;
    const size_t rb0 = (size_t)(s0 + m0r) * DIM + h * DHEAD;
    const size_t rb1 = rb0 + 8 * DIM;
    #pragma unroll
    for (int j = 0; j < 8; j++) {
        int d = j * 8 + (lane & 3) * 2;
        if (v0)
            *(uint32_t*)&oout[rb0 + d] = packhi(ov[j][0] * inv0, ov[j][1] * inv0);
        if (v1)
            *(uint32_t*)&oout[rb1 + d] = packhi(ov[j][2] * inv1, ov[j][3] * inv1);
    }
}

// ======================= launch ==================================================
extern "C" void kernel_launch(void* const* d_in, const int* in_sizes, int n_in,
                              void* d_out, int out_size) {
    const float* z     = (const float*)d_in[0];
    const int*   src   = (const int*)  d_in[1];
    const float* gamma = (const float*)d_in[2];
    const float* beta  = (const float*)d_in[3];
    const float* Wq    = (const float*)d_in[4];
    const float* Wk    = (const float*)d_in[5];
    const float* Wv    = (const float*)d_in[6];
    const float* Wo    = (const float*)d_in[7];
    const float* bo    = (const float*)d_in[8];
    float* out = (float*)d_out;

    cudaFuncSetAttribute(attn_kernel, cudaFuncAttributeMaxDynamicSharedMemorySize, A_SMEM);
    cudaFuncSetAttribute(gemm_mma<0>, cudaFuncAttributeMaxDynamicSharedMemorySize, G_SMEM_TOT);
    cudaFuncSetAttribute(gemm_mma<1>, cudaFuncAttributeMaxDynamicSharedMemorySize, G_SMEM_TOT);

    __half *a_p, *wt_p, *q_p, *k_p, *v_p;
    cudaGetSymbolAddress((void**)&a_p,  g_a);
    cudaGetSymbolAddress((void**)&wt_p, g_wt);
    cudaGetSymbolAddress((void**)&q_p,  g_q);
    cudaGetSymbolAddress((void**)&k_p,  g_k);
    cudaGetSymbolAddress((void**)&v_p,  g_v);

    starts_kernel<<<1, 64>>>(src);
    ln_kernel<<<NTOT / 8, 256>>>(z, gamma, beta);
    wconv_kernel<<<dim3(16, 16, 4), dim3(32, 8)>>>(Wq, Wk, Wv, Wo);

    // fused Q/K/V projections (single-product fp16)
    gemm_mma<0><<<dim3(4, 96, 3), 256, G_SMEM_TOT>>>(
        a_p, wt_p, q_p, k_p, v_p, nullptr, nullptr);

    attn_kernel<<<dim3(8, HEADS, NBATCH), 128, A_SMEM>>>(q_p, k_p, v_p, a_p);

    // output projection (fp32 + bias)
    gemm_mma<1><<<dim3(4, 96, 1), 256, G_SMEM_TOT>>>(
        a_p, wt_p + 3 * DIN * DIM,
        nullptr, nullptr, nullptr, out, bo);
}

// round 15
// speedup vs baseline: 2.9132x; 1.0633x over previous
#include <cuda_runtime.h>
#include <cuda_fp16.h>
#include <cstdint>

#define NTOT   12288
#define DIN    512
#define DIM    512
#define HEADS  8
#define DHEAD  64
#define NBATCH 32

// ======================= PTX helpers (sm_80 ISA, valid at compute_103) ==========
__device__ __forceinline__ uint32_t smem_u32(const void* p) {
    uint32_t a;
    asm("{ .reg .u64 t; cvta.to.shared.u64 t, %1; cvt.u32.u64 %0, t; }" : "=r"(a) : "l"(p));
    return a;
}
__device__ __forceinline__ void ldsm4(uint32_t* r, uint32_t addr) {
    asm volatile("ldmatrix.sync.aligned.m8n8.x4.shared.b16 {%0,%1,%2,%3}, [%4];"
        : "=r"(r[0]), "=r"(r[1]), "=r"(r[2]), "=r"(r[3]) : "r"(addr));
}
__device__ __forceinline__ void ldsm4t(uint32_t* r, uint32_t addr) {
    asm volatile("ldmatrix.sync.aligned.m8n8.x4.trans.shared.b16 {%0,%1,%2,%3}, [%4];"
        : "=r"(r[0]), "=r"(r[1]), "=r"(r[2]), "=r"(r[3]) : "r"(addr));
}
__device__ __forceinline__ void mma16816(float* c, const uint32_t* a,
                                         uint32_t b0, uint32_t b1) {
    asm volatile("mma.sync.aligned.m16n8k16.row.col.f32.f16.f16.f32 "
        "{%0,%1,%2,%3}, {%4,%5,%6,%7}, {%8,%9}, {%0,%1,%2,%3};"
        : "+f"(c[0]), "+f"(c[1]), "+f"(c[2]), "+f"(c[3])
        : "r"(a[0]), "r"(a[1]), "r"(a[2]), "r"(a[3]), "r"(b0), "r"(b1));
}
__device__ __forceinline__ void cpa16(uint32_t s, const void* g) {
    asm volatile("cp.async.cg.shared.global [%0], [%1], 16;" :: "r"(s), "l"(g));
}
__device__ __forceinline__ void cpa16z(uint32_t s, const void* g, bool p) {
    int sz = p ? 16 : 0;
    asm volatile("cp.async.cg.shared.global [%0], [%1], 16, %2;" :: "r"(s), "l"(g), "r"(sz));
}
#define CP_COMMIT() asm volatile("cp.async.commit_group;" ::: "memory")
#define CP_WAIT(n)  asm volatile("cp.async.wait_group %0;" :: "n"(n) : "memory")

__device__ __forceinline__ uint32_t packhi(float x, float y) {
    __half2 h = __floats2half2_rn(x, y);
    return *(uint32_t*)&h;
}

// ======================= scratch =================================================
__device__ __half g_a [NTOT * DIN];      // LN output / attention output (fp16)
__device__ __half g_wt[4 * DIN * DIM];   // [mat][n][k], single fp16
__device__ __half g_q [NTOT * DIM];
__device__ __half g_k [NTOT * DIM];
__device__ __half g_v [NTOT * DIM];
__device__ int g_starts[NBATCH + 1];

// ======================= starts ==================================================
__global__ void starts_kernel(const int* __restrict__ src) {
    int b = threadIdx.x;
    if (b > NBATCH) return;
    int lo = 0, hi = NTOT;
    while (lo < hi) { int mid = (lo + hi) >> 1; if (src[mid] < b) lo = mid + 1; else hi = mid; }
    g_starts[b] = lo;
}

// ======================= LayerNorm (warp per row) -> fp16 ========================
__global__ void __launch_bounds__(256) ln_kernel(const float* __restrict__ z,
                                                 const float* __restrict__ gamma,
                                                 const float* __restrict__ beta) {
    const int row  = blockIdx.x * 8 + (threadIdx.x >> 5);
    const int lane = threadIdx.x & 31;
    const float* zr = z + (size_t)row * DIN;
    float4 v[4];
    float s = 0.f, ss = 0.f;
    #pragma unroll
    for (int i = 0; i < 4; i++) {
        v[i] = ((const float4*)zr)[lane + i * 32];
        s  += v[i].x + v[i].y + v[i].z + v[i].w;
        ss += v[i].x*v[i].x + v[i].y*v[i].y + v[i].z*v[i].z + v[i].w*v[i].w;
    }
    #pragma unroll
    for (int off = 16; off; off >>= 1) {
        s  += __shfl_xor_sync(0xffffffffu, s,  off);
        ss += __shfl_xor_sync(0xffffffffu, ss, off);
    }
    const float mu  = s * (1.0f / DIN);
    const float var = ss * (1.0f / DIN) - mu * mu;
    const float inv = rsqrtf(var + 1e-5f);
    #pragma unroll
    for (int i = 0; i < 4; i++) {
        const int c4 = lane + i * 32;
        float4 g  = ((const float4*)gamma)[c4];
        float4 be = ((const float4*)beta)[c4];
        float o0 = (v[i].x - mu) * inv * g.x + be.x;
        float o1 = (v[i].y - mu) * inv * g.y + be.y;
        float o2 = (v[i].z - mu) * inv * g.z + be.z;
        float o3 = (v[i].w - mu) * inv * g.w + be.w;
        size_t base = (size_t)row * DIN + c4 * 4;
        *(uint32_t*)&g_a[base]     = packhi(o0, o1);
        *(uint32_t*)&g_a[base + 2] = packhi(o2, o3);
    }
}

// ======================= weight transpose (single fp16) ==========================
__global__ void __launch_bounds__(256) wconv_kernel(const float* __restrict__ Wq,
                                                    const float* __restrict__ Wk,
                                                    const float* __restrict__ Wv,
                                                    const float* __restrict__ Wo) {
    __shared__ float t[32][33];
    const float* W = blockIdx.z == 0 ? Wq : blockIdx.z == 1 ? Wk : blockIdx.z == 2 ? Wv : Wo;
    const int bx = blockIdx.x, by = blockIdx.y;
    const int tx = threadIdx.x, ty = threadIdx.y;    // 32 x 8
    #pragma unroll
    for (int i = 0; i < 4; i++)
        t[ty + 8 * i][tx] = W[(size_t)(by * 32 + ty + 8 * i) * DIM + bx * 32 + tx];
    __syncthreads();
    size_t mbase = (size_t)blockIdx.z * DIN * DIM;
    #pragma unroll
    for (int i = 0; i < 4; i++) {
        int n = bx * 32 + ty + 8 * i;
        int k = by * 32 + tx;
        g_wt[mbase + (size_t)n * DIN + k] = __float2half(t[tx][ty + 8 * i]);
    }
}

// ======================= fp16 single-product GEMM, cp.async 2-stage ==============
// C = A @ W   CTA tile 128x128, k-chunk 64, 8 warps (32x64), 2 CTAs/SM.
// 2 tiles/stage x 2 stages = 73.7 KB -> cross-CTA overlap AND prefetch pipelining.
#define GLDS 72
#define G_TILE_B  (128 * GLDS * 2)     // 18432 B per tile
#define G_STAGE_B (2 * G_TILE_B)       // 36864 B per stage
#define G_SMEM_TOT (2 * G_STAGE_B)     // 73728 B -> 2 CTAs/SM

// EPI 0: write fp16 per-mat.  EPI 1: write fp32 + bias.
template<int EPI>
__global__ void __launch_bounds__(256, 2)
gemm_mma(const __half* __restrict__ A, const __half* __restrict__ Wt,
         __half* o0, __half* o1, __half* o2,
         float* fout, const float* __restrict__ bias) {
    extern __shared__ char smem[];
    const uint32_t sb = smem_u32(smem);
    const int tid  = threadIdx.x;
    const int wid  = tid >> 5;
    const int lane = tid & 31;
    const int mwarp = wid & 3;
    const int nwarp = wid >> 2;
    const int nBase = blockIdx.x * 128;
    const int mBase = blockIdx.y * 128;
    const int mat = blockIdx.z;
    const int lrow = lane & 15;
    const int lcol = (lane >> 4) * 8;

    __half* ohp = (mat == 0) ? o0 : (mat == 1) ? o1 : o2;

    const __half* gsrc[2] = {
        A + (size_t)mBase * DIN,
        Wt + (size_t)mat * DIN * DIM + (size_t)nBase * DIN };

    float acc[2][8][4];
    #pragma unroll
    for (int a = 0; a < 2; a++)
        #pragma unroll
        for (int b = 0; b < 8; b++)
            #pragma unroll
            for (int c = 0; c < 4; c++) acc[a][b][c] = 0.f;

    // stage loader: 2 tiles x [128 rows x 64 fp16]; 8 cp.async per thread
    auto load_chunk = [&](int st, int kb) {
        const uint32_t sbase = sb + st * G_STAGE_B;
        #pragma unroll
        for (int t = 0; t < 2; t++) {
            #pragma unroll
            for (int r = 0; r < 4; r++) {
                int idx = tid + r * 256;          // 0..1023
                int row = idx >> 3;               // 0..127
                int j   = idx & 7;                // 16B units
                cpa16(sbase + t * G_TILE_B + row * (GLDS * 2) + j * 16,
                      gsrc[t] + kb + (size_t)row * DIN + j * 8);
            }
        }
    };

    load_chunk(0, 0); CP_COMMIT();

    for (int chunk = 0; chunk < 8; chunk++) {
        if (chunk < 7) { load_chunk((chunk + 1) & 1, (chunk + 1) * 64); CP_COMMIT(); CP_WAIT(1); }
        else           { CP_WAIT(0); }
        __syncthreads();
        const uint32_t sbs = sb + (chunk & 1) * G_STAGE_B;

        #pragma unroll
        for (int ks = 0; ks < 4; ks++) {
            const int kk = ks * 16 + lcol;
            uint32_t ah[2][4];
            #pragma unroll
            for (int mt = 0; mt < 2; mt++) {
                uint32_t off = (uint32_t)((mwarp * 32 + mt * 16 + lrow) * GLDS + kk) * 2;
                ldsm4(ah[mt], sbs + off);
            }
            #pragma unroll
            for (int nb = 0; nb < 4; nb++) {
                uint32_t off = (uint32_t)((nwarp * 64 + nb * 16 + lrow) * GLDS + kk) * 2;
                uint32_t wv[4];
                ldsm4(wv, sbs + G_TILE_B + off);
                #pragma unroll
                for (int mt = 0; mt < 2; mt++) {
                    mma16816(acc[mt][2 * nb],     ah[mt], wv[0], wv[2]);
                    mma16816(acc[mt][2 * nb + 1], ah[mt], wv[1], wv[3]);
                }
            }
        }
        __syncthreads();
    }

    const int erow = lane >> 2;
    const int ecol = (lane & 3) * 2;
    #pragma unroll
    for (int mt = 0; mt < 2; mt++) {
        int r0 = mBase + mwarp * 32 + mt * 16 + erow;
        #pragma unroll
        for (int n8 = 0; n8 < 8; n8++) {
            int col = nBase + nwarp * 64 + n8 * 8 + ecol;
            float c0 = acc[mt][n8][0], c1 = acc[mt][n8][1];
            float c2 = acc[mt][n8][2], c3 = acc[mt][n8][3];
            if (EPI == 1) {
                float2 bb = *(const float2*)&bias[col];
                *(float2*)&fout[(size_t)r0 * DIM + col]       = make_float2(c0 + bb.x, c1 + bb.y);
                *(float2*)&fout[(size_t)(r0 + 8) * DIM + col] = make_float2(c2 + bb.x, c3 + bb.y);
            } else {
                *(uint32_t*)&ohp[(size_t)r0 * DIM + col]       = packhi(c0, c1);
                *(uint32_t*)&ohp[(size_t)(r0 + 8) * DIM + col] = packhi(c2, c3);
            }
        }
    }
}

// ======================= tensor-core flash attention (single-product fp16) =======
#define AP 72
#define AT_B (64 * AP * 2)                 // 9216
#define A_SMEM (AT_B + 2 * 2 * AT_B)       // 46080: Q + 2 stages x (K,V)

__global__ void __launch_bounds__(128)
attn_kernel(const __half* __restrict__ q, const __half* __restrict__ k,
            const __half* __restrict__ v, __half* __restrict__ oout) {
    extern __shared__ char smem[];
    const uint32_t sb = smem_u32(smem);
    const int qt = blockIdx.x, h = blockIdx.y, b = blockIdx.z;
    const int s0 = g_starts[b];
    const int ng = g_starts[b + 1] - s0;
    const int q0 = qt * 64;
    if (q0 >= ng) return;
    const int tid = threadIdx.x;
    const int w = tid >> 5, lane = tid & 31;
    const int lrow = lane & 15, lcol = (lane >> 4) * 8;

    const uint32_t sQ = sb;

    {
        const size_t gb = (size_t)(s0 + q0) * DIM + h * DHEAD;
        #pragma unroll
        for (int r = 0; r < 4; r++) {
            int idx = tid + r * 128;
            int m = idx >> 3, j = idx & 7;
            bool p = (q0 + m) < ng;
            cpa16z(sQ + (uint32_t)(m * AP + j * 8) * 2, q + gb + (size_t)m * DIM + j * 8, p);
        }
    }

    const __half* kvsrc[2] = { k, v };
    auto load_kv = [&](int st, int kb) {
        uint32_t sbase = sb + AT_B + st * 2 * AT_B;
        const size_t gb = (size_t)(s0 + kb) * DIM + h * DHEAD;
        #pragma unroll
        for (int t = 0; t < 2; t++)
            #pragma unroll
            for (int r = 0; r < 4; r++) {
                int idx = tid + r * 128;
                int m = idx >> 3, j = idx & 7;
                bool p = (kb + m) < ng;
                cpa16z(sbase + t * AT_B + (uint32_t)(m * AP + j * 8) * 2,
                       kvsrc[t] + gb + (size_t)m * DIM + j * 8, p);
            }
    };

    load_kv(0, 0); CP_COMMIT();

    float sv[8][4], ov[8][4];
    #pragma unroll
    for (int j = 0; j < 8; j++)
        #pragma unroll
        for (int c = 0; c < 4; c++) ov[j][c] = 0.f;
    float rm0 = -1e30f, rm1 = -1e30f, rl0 = 0.f, rl1 = 0.f;

    const int nchunks = (ng + 63) >> 6;
    for (int c = 0; c < nchunks; c++) {
        if (c + 1 < nchunks) { load_kv((c + 1) & 1, (c + 1) * 64); CP_COMMIT(); CP_WAIT(1); }
        else                 { CP_WAIT(0); }
        __syncthreads();
        const uint32_t sK = sb + AT_B + (c & 1) * 2 * AT_B;
        const uint32_t sV = sK + AT_B;

        #pragma unroll
        for (int j = 0; j < 8; j++)
            #pragma unroll
            for (int cc = 0; cc < 4; cc++) sv[j][cc] = 0.f;
        #pragma unroll
        for (int ks = 0; ks < 4; ks++) {
            const int kk = ks * 16 + lcol;
            uint32_t qh[4];
            ldsm4(qh, sQ + (uint32_t)((w * 16 + lrow) * AP + kk) * 2);
            #pragma unroll
            for (int n16 = 0; n16 < 4; n16++) {
                uint32_t kh[4];
                ldsm4(kh, sK + (uint32_t)((n16 * 16 + lrow) * AP + kk) * 2);
                mma16816(sv[2 * n16],     qh, kh[0], kh[2]);
                mma16816(sv[2 * n16 + 1], qh, kh[1], kh[3]);
            }
        }

        const int kb = c * 64;
        #pragma unroll
        for (int j = 0; j < 8; j++) {
            int col = kb + j * 8 + (lane & 3) * 2;
            bool v0 = col < ng, v1 = (col + 1) < ng;
            sv[j][0] = v0 ? sv[j][0] * 0.125f : -1e30f;
            sv[j][1] = v1 ? sv[j][1] * 0.125f : -1e30f;
            sv[j][2] = v0 ? sv[j][2] * 0.125f : -1e30f;
            sv[j][3] = v1 ? sv[j][3] * 0.125f : -1e30f;
        }
        float m0 = -1e30f, m1 = -1e30f;
        #pragma unroll
        for (int j = 0; j < 8; j++) {
            m0 = fmaxf(m0, fmaxf(sv[j][0], sv[j][1]));
            m1 = fmaxf(m1, fmaxf(sv[j][2], sv[j][3]));
        }
        m0 = fmaxf(m0, __shfl_xor_sync(0xffffffffu, m0, 1));
        m0 = fmaxf(m0, __shfl_xor_sync(0xffffffffu, m0, 2));
        m1 = fmaxf(m1, __shfl_xor_sync(0xffffffffu, m1, 1));
        m1 = fmaxf(m1, __shfl_xor_sync(0xffffffffu, m1, 2));
        float nm0 = fmaxf(rm0, m0), nm1 = fmaxf(rm1, m1);
        float sc0 = __expf(rm0 - nm0), sc1 = __expf(rm1 - nm1);
        rm0 = nm0; rm1 = nm1;
        float l0 = 0.f, l1 = 0.f;
        #pragma unroll
        for (int j = 0; j < 8; j++) {
            sv[j][0] = __expf(sv[j][0] - nm0); l0 += sv[j][0];
            sv[j][1] = __expf(sv[j][1] - nm0); l0 += sv[j][1];
            sv[j][2] = __expf(sv[j][2] - nm1); l1 += sv[j][2];
            sv[j][3] = __expf(sv[j][3] - nm1); l1 += sv[j][3];
        }
        l0 += __shfl_xor_sync(0xffffffffu, l0, 1);
        l0 += __shfl_xor_sync(0xffffffffu, l0, 2);
        l1 += __shfl_xor_sync(0xffffffffu, l1, 1);
        l1 += __shfl_xor_sync(0xffffffffu, l1, 2);
        rl0 = rl0 * sc0 + l0;
        rl1 = rl1 * sc1 + l1;
        #pragma unroll
        for (int j = 0; j < 8; j++) {
            ov[j][0] *= sc0; ov[j][1] *= sc0;
            ov[j][2] *= sc1; ov[j][3] *= sc1;
        }

        #pragma unroll
        for (int ks = 0; ks < 4; ks++) {
            uint32_t ah[4];
            ah[0] = packhi(sv[2 * ks][0],     sv[2 * ks][1]);
            ah[1] = packhi(sv[2 * ks][2],     sv[2 * ks][3]);
            ah[2] = packhi(sv[2 * ks + 1][0], sv[2 * ks + 1][1]);
            ah[3] = packhi(sv[2 * ks + 1][2], sv[2 * ks + 1][3]);
            #pragma unroll
            for (int d16 = 0; d16 < 4; d16++) {
                uint32_t off = (uint32_t)((ks * 16 + lrow) * AP + d16 * 16 + lcol) * 2;
                uint32_t vh[4];
                ldsm4t(vh, sV + off);
                mma16816(ov[2 * d16],     ah, vh[0], vh[1]);
                mma16816(ov[2 * d16 + 1], ah, vh[2], vh[3]);
            }
        }
        __syncthreads();
    }

    const float inv0 = 1.f / rl0, inv1 = 1.f / rl1;
    const int m0r = q0 + w * 16 + (lane >> 2);
    const bool v0 = m0r < ng, v1 = (m0r + 8) < ng;
    const size_t rb0 = (size_t)(s0 + m0r) * DIM + h * DHEAD;
    const size_t rb1 = rb0 + 8 * DIM;
    #pragma unroll
    for (int j = 0; j < 8; j++) {
        int d = j * 8 + (lane & 3) * 2;
        if (v0)
            *(uint32_t*)&oout[rb0 + d] = packhi(ov[j][0] * inv0, ov[j][1] * inv0);
        if (v1)
            *(uint32_t*)&oout[rb1 + d] = packhi(ov[j][2] * inv1, ov[j][3] * inv1);
    }
}

// ======================= launch ==================================================
extern "C" void kernel_launch(void* const* d_in, const int* in_sizes, int n_in,
                              void* d_out, int out_size) {
    const float* z     = (const float*)d_in[0];
    const int*   src   = (const int*)  d_in[1];
    const float* gamma = (const float*)d_in[2];
    const float* beta  = (const float*)d_in[3];
    const float* Wq    = (const float*)d_in[4];
    const float* Wk    = (const float*)d_in[5];
    const float* Wv    = (const float*)d_in[6];
    const float* Wo    = (const float*)d_in[7];
    const float* bo    = (const float*)d_in[8];
    float* out = (float*)d_out;

    cudaFuncSetAttribute(attn_kernel, cudaFuncAttributeMaxDynamicSharedMemorySize, A_SMEM);
    cudaFuncSetAttribute(gemm_mma<0>, cudaFuncAttributeMaxDynamicSharedMemorySize, G_SMEM_TOT);
    cudaFuncSetAttribute(gemm_mma<1>, cudaFuncAttributeMaxDynamicSharedMemorySize, G_SMEM_TOT);

    __half *a_p, *wt_p, *q_p, *k_p, *v_p;
    cudaGetSymbolAddress((void**)&a_p,  g_a);
    cudaGetSymbolAddress((void**)&wt_p, g_wt);
    cudaGetSymbolAddress((void**)&q_p,  g_q);
    cudaGetSymbolAddress((void**)&k_p,  g_k);
    cudaGetSymbolAddress((void**)&v_p,  g_v);

    starts_kernel<<<1, 64>>>(src);
    ln_kernel<<<NTOT / 8, 256>>>(z, gamma, beta);
    wconv_kernel<<<dim3(16, 16, 4), dim3(32, 8)>>>(Wq, Wk, Wv, Wo);

    // fused Q/K/V projections (single-product fp16, cp.async 2-stage, 2 CTAs/SM)
    gemm_mma<0><<<dim3(4, 96, 3), 256, G_SMEM_TOT>>>(
        a_p, wt_p, q_p, k_p, v_p, nullptr, nullptr);

    attn_kernel<<<dim3(8, HEADS, NBATCH), 128, A_SMEM>>>(q_p, k_p, v_p, a_p);

    // output projection (fp32 + bias)
    gemm_mma<1><<<dim3(4, 96, 1), 256, G_SMEM_TOT>>>(
        a_p, wt_p + 3 * DIN * DIM,
        nullptr, nullptr, nullptr, out, bo);
}

// round 16
// speedup vs baseline: 2.9740x; 1.0209x over previous
#include <cuda_runtime.h>
#include <cuda_fp16.h>
#include <cstdint>

#define NTOT   12288
#define DIN    512
#define DIM    512
#define HEADS  8
#define DHEAD  64
#define NBATCH 32

// ======================= PTX helpers (sm_80 ISA, valid at compute_103) ==========
__device__ __forceinline__ uint32_t smem_u32(const void* p) {
    uint32_t a;
    asm("{ .reg .u64 t; cvta.to.shared.u64 t, %1; cvt.u32.u64 %0, t; }" : "=r"(a) : "l"(p));
    return a;
}
__device__ __forceinline__ void ldsm4(uint32_t* r, uint32_t addr) {
    asm volatile("ldmatrix.sync.aligned.m8n8.x4.shared.b16 {%0,%1,%2,%3}, [%4];"
        : "=r"(r[0]), "=r"(r[1]), "=r"(r[2]), "=r"(r[3]) : "r"(addr));
}
__device__ __forceinline__ void ldsm4t(uint32_t* r, uint32_t addr) {
    asm volatile("ldmatrix.sync.aligned.m8n8.x4.trans.shared.b16 {%0,%1,%2,%3}, [%4];"
        : "=r"(r[0]), "=r"(r[1]), "=r"(r[2]), "=r"(r[3]) : "r"(addr));
}
__device__ __forceinline__ void mma16816(float* c, const uint32_t* a,
                                         uint32_t b0, uint32_t b1) {
    asm volatile("mma.sync.aligned.m16n8k16.row.col.f32.f16.f16.f32 "
        "{%0,%1,%2,%3}, {%4,%5,%6,%7}, {%8,%9}, {%0,%1,%2,%3};"
        : "+f"(c[0]), "+f"(c[1]), "+f"(c[2]), "+f"(c[3])
        : "r"(a[0]), "r"(a[1]), "r"(a[2]), "r"(a[3]), "r"(b0), "r"(b1));
}
__device__ __forceinline__ void cpa16(uint32_t s, const void* g) {
    asm volatile("cp.async.cg.shared.global [%0], [%1], 16;" :: "r"(s), "l"(g));
}
__device__ __forceinline__ void cpa16z(uint32_t s, const void* g, bool p) {
    int sz = p ? 16 : 0;
    asm volatile("cp.async.cg.shared.global [%0], [%1], 16, %2;" :: "r"(s), "l"(g), "r"(sz));
}
#define CP_COMMIT() asm volatile("cp.async.commit_group;" ::: "memory")
#define CP_WAIT(n)  asm volatile("cp.async.wait_group %0;" :: "n"(n) : "memory")

__device__ __forceinline__ uint32_t packhi(float x, float y) {
    __half2 h = __floats2half2_rn(x, y);
    return *(uint32_t*)&h;
}

// ======================= scratch =================================================
__device__ __half g_a [NTOT * DIN];      // LN output / attention output (fp16)
__device__ __half g_wt[4 * DIN * DIM];   // [mat][n][k], single fp16
__device__ __half g_q [NTOT * DIM];
__device__ __half g_k [NTOT * DIM];
__device__ __half g_v [NTOT * DIM];
__device__ int g_starts[NBATCH + 1];

// ======================= fused prep: LN + weight transpose + starts ==============
// blocks [0, 1536): LayerNorm (8 rows each, warp per row)
// blocks [1536, 2560): weight transpose+cvt (32x32 tile each)
// block  2560: starts (binary search)
#define LN_BLOCKS 1536
#define WC_BLOCKS 1024

__global__ void __launch_bounds__(256)
prep_kernel(const float* __restrict__ z, const float* __restrict__ gamma,
            const float* __restrict__ beta,
            const float* __restrict__ Wq, const float* __restrict__ Wk,
            const float* __restrict__ Wv, const float* __restrict__ Wo,
            const int* __restrict__ src) {
    __shared__ float t[32][33];
    const int blk = blockIdx.x;
    const int tid = threadIdx.x;

    if (blk < LN_BLOCKS) {
        // ---- LayerNorm, warp per row ----
        const int row  = blk * 8 + (tid >> 5);
        const int lane = tid & 31;
        const float* zr = z + (size_t)row * DIN;
        float4 v[4];
        float s = 0.f, ss = 0.f;
        #pragma unroll
        for (int i = 0; i < 4; i++) {
            v[i] = ((const float4*)zr)[lane + i * 32];
            s  += v[i].x + v[i].y + v[i].z + v[i].w;
            ss += v[i].x*v[i].x + v[i].y*v[i].y + v[i].z*v[i].z + v[i].w*v[i].w;
        }
        #pragma unroll
        for (int off = 16; off; off >>= 1) {
            s  += __shfl_xor_sync(0xffffffffu, s,  off);
            ss += __shfl_xor_sync(0xffffffffu, ss, off);
        }
        const float mu  = s * (1.0f / DIN);
        const float var = ss * (1.0f / DIN) - mu * mu;
        const float inv = rsqrtf(var + 1e-5f);
        #pragma unroll
        for (int i = 0; i < 4; i++) {
            const int c4 = lane + i * 32;
            float4 g  = ((const float4*)gamma)[c4];
            float4 be = ((const float4*)beta)[c4];
            float o0 = (v[i].x - mu) * inv * g.x + be.x;
            float o1 = (v[i].y - mu) * inv * g.y + be.y;
            float o2 = (v[i].z - mu) * inv * g.z + be.z;
            float o3 = (v[i].w - mu) * inv * g.w + be.w;
            size_t base = (size_t)row * DIN + c4 * 4;
            *(uint32_t*)&g_a[base]     = packhi(o0, o1);
            *(uint32_t*)&g_a[base + 2] = packhi(o2, o3);
        }
    } else if (blk < LN_BLOCKS + WC_BLOCKS) {
        // ---- weight transpose + fp32->fp16 ----
        const int w = blk - LN_BLOCKS;        // 0..1023
        const int bx = w & 15;
        const int by = (w >> 4) & 15;
        const int mz = w >> 8;                // 0..3
        const float* W = mz == 0 ? Wq : mz == 1 ? Wk : mz == 2 ? Wv : Wo;
        const int tx = tid & 31, ty = tid >> 5;   // 32 x 8
        #pragma unroll
        for (int i = 0; i < 4; i++)
            t[ty + 8 * i][tx] = W[(size_t)(by * 32 + ty + 8 * i) * DIM + bx * 32 + tx];
        __syncthreads();
        size_t mbase = (size_t)mz * DIN * DIM;
        #pragma unroll
        for (int i = 0; i < 4; i++) {
            int n = bx * 32 + ty + 8 * i;
            int k = by * 32 + tx;
            g_wt[mbase + (size_t)n * DIN + k] = __float2half(t[tx][ty + 8 * i]);
        }
    } else {
        // ---- starts: lower_bound over sorted src ----
        int b = tid;
        if (b <= NBATCH) {
            int lo = 0, hi = NTOT;
            while (lo < hi) { int mid = (lo + hi) >> 1; if (src[mid] < b) lo = mid + 1; else hi = mid; }
            g_starts[b] = lo;
        }
    }
}

// ======================= fp16 single-product GEMM, cp.async 3-stage ==============
// C = A @ W   CTA tile 128x128, k-chunk 64, 8 warps (32x64), 2 CTAs/SM.
// 3 stages x 36.9 KB = 110.6 KB/CTA; 1 syncthreads per chunk (canonical multistage).
#define GLDS 72
#define G_TILE_B  (128 * GLDS * 2)     // 18432 B per tile
#define G_STAGE_B (2 * G_TILE_B)       // 36864 B per stage
#define G_SMEM_TOT (3 * G_STAGE_B)     // 110592 B -> 2 CTAs/SM (221 KB <= 228)

// EPI 0: write fp16 per-mat.  EPI 1: write fp32 + bias.
template<int EPI>
__global__ void __launch_bounds__(256, 2)
gemm_mma(const __half* __restrict__ A, const __half* __restrict__ Wt,
         __half* o0, __half* o1, __half* o2,
         float* fout, const float* __restrict__ bias) {
    extern __shared__ char smem[];
    const uint32_t sb = smem_u32(smem);
    const int tid  = threadIdx.x;
    const int wid  = tid >> 5;
    const int lane = tid & 31;
    const int mwarp = wid & 3;
    const int nwarp = wid >> 2;
    const int nBase = blockIdx.x * 128;
    const int mBase = blockIdx.y * 128;
    const int mat = blockIdx.z;
    const int lrow = lane & 15;
    const int lcol = (lane >> 4) * 8;

    __half* ohp = (mat == 0) ? o0 : (mat == 1) ? o1 : o2;

    const __half* gsrc[2] = {
        A + (size_t)mBase * DIN,
        Wt + (size_t)mat * DIN * DIM + (size_t)nBase * DIN };

    float acc[2][8][4];
    #pragma unroll
    for (int a = 0; a < 2; a++)
        #pragma unroll
        for (int b = 0; b < 8; b++)
            #pragma unroll
            for (int c = 0; c < 4; c++) acc[a][b][c] = 0.f;

    // stage loader: 2 tiles x [128 rows x 64 fp16]; 8 cp.async per thread
    auto load_chunk = [&](int st, int kb) {
        const uint32_t sbase = sb + st * G_STAGE_B;
        #pragma unroll
        for (int t = 0; t < 2; t++) {
            #pragma unroll
            for (int r = 0; r < 4; r++) {
                int idx = tid + r * 256;          // 0..1023
                int row = idx >> 3;               // 0..127
                int j   = idx & 7;                // 16B units
                cpa16(sbase + t * G_TILE_B + row * (GLDS * 2) + j * 16,
                      gsrc[t] + kb + (size_t)row * DIN + j * 8);
            }
        }
    };

    load_chunk(0, 0);  CP_COMMIT();
    load_chunk(1, 64); CP_COMMIT();

    for (int chunk = 0; chunk < 8; chunk++) {
        if (chunk < 7) { CP_WAIT(1); }
        else           { CP_WAIT(0); }
        __syncthreads();
        // issue next-next chunk AFTER the sync: its target stage (chunk+2)%3 ==
        // (chunk-1)%3 was fully consumed by compute(chunk-1), which all threads
        // finished before this sync.
        if (chunk < 6) { load_chunk((chunk + 2) % 3, (chunk + 2) * 64); CP_COMMIT(); }
        const uint32_t sbs = sb + (chunk % 3) * G_STAGE_B;

        #pragma unroll
        for (int ks = 0; ks < 4; ks++) {
            const int kk = ks * 16 + lcol;
            uint32_t ah[2][4];
            #pragma unroll
            for (int mt = 0; mt < 2; mt++) {
                uint32_t off = (uint32_t)((mwarp * 32 + mt * 16 + lrow) * GLDS + kk) * 2;
                ldsm4(ah[mt], sbs + off);
            }
            #pragma unroll
            for (int nb = 0; nb < 4; nb++) {
                uint32_t off = (uint32_t)((nwarp * 64 + nb * 16 + lrow) * GLDS + kk) * 2;
                uint32_t wv[4];
                ldsm4(wv, sbs + G_TILE_B + off);
                #pragma unroll
                for (int mt = 0; mt < 2; mt++) {
                    mma16816(acc[mt][2 * nb],     ah[mt], wv[0], wv[2]);
                    mma16816(acc[mt][2 * nb + 1], ah[mt], wv[1], wv[3]);
                }
            }
        }
        // no trailing syncthreads: next iteration's sync provides the barrier
    }

    const int erow = lane >> 2;
    const int ecol = (lane & 3) * 2;
    #pragma unroll
    for (int mt = 0; mt < 2; mt++) {
        int r0 = mBase + mwarp * 32 + mt * 16 + erow;
        #pragma unroll
        for (int n8 = 0; n8 < 8; n8++) {
            int col = nBase + nwarp * 64 + n8 * 8 + ecol;
            float c0 = acc[mt][n8][0], c1 = acc[mt][n8][1];
            float c2 = acc[mt][n8][2], c3 = acc[mt][n8][3];
            if (EPI == 1) {
                float2 bb = *(const float2*)&bias[col];
                *(float2*)&fout[(size_t)r0 * DIM + col]       = make_float2(c0 + bb.x, c1 + bb.y);
                *(float2*)&fout[(size_t)(r0 + 8) * DIM + col] = make_float2(c2 + bb.x, c3 + bb.y);
            } else {
                *(uint32_t*)&ohp[(size_t)r0 * DIM + col]       = packhi(c0, c1);
                *(uint32_t*)&ohp[(size_t)(r0 + 8) * DIM + col] = packhi(c2, c3);
            }
        }
    }
}

// ======================= tensor-core flash attention (single-product fp16) =======
#define AP 72
#define AT_B (64 * AP * 2)                 // 9216
#define A_SMEM (AT_B + 2 * 2 * AT_B)       // 46080: Q + 2 stages x (K,V)

__global__ void __launch_bounds__(128)
attn_kernel(const __half* __restrict__ q, const __half* __restrict__ k,
            const __half* __restrict__ v, __half* __restrict__ oout) {
    extern __shared__ char smem[];
    const uint32_t sb = smem_u32(smem);
    const int qt = blockIdx.x, h = blockIdx.y, b = blockIdx.z;
    const int s0 = g_starts[b];
    const int ng = g_starts[b + 1] - s0;
    const int q0 = qt * 64;
    if (q0 >= ng) return;
    const int tid = threadIdx.x;
    const int w = tid >> 5, lane = tid & 31;
    const int lrow = lane & 15, lcol = (lane >> 4) * 8;

    const uint32_t sQ = sb;

    {
        const size_t gb = (size_t)(s0 + q0) * DIM + h * DHEAD;
        #pragma unroll
        for (int r = 0; r < 4; r++) {
            int idx = tid + r * 128;
            int m = idx >> 3, j = idx & 7;
            bool p = (q0 + m) < ng;
            cpa16z(sQ + (uint32_t)(m * AP + j * 8) * 2, q + gb + (size_t)m * DIM + j * 8, p);
        }
    }

    const __half* kvsrc[2] = { k, v };
    auto load_kv = [&](int st, int kb) {
        uint32_t sbase = sb + AT_B + st * 2 * AT_B;
        const size_t gb = (size_t)(s0 + kb) * DIM + h * DHEAD;
        #pragma unroll
        for (int t = 0; t < 2; t++)
            #pragma unroll
            for (int r = 0; r < 4; r++) {
                int idx = tid + r * 128;
                int m = idx >> 3, j = idx & 7;
                bool p = (kb + m) < ng;
                cpa16z(sbase + t * AT_B + (uint32_t)(m * AP + j * 8) * 2,
                       kvsrc[t] + gb + (size_t)m * DIM + j * 8, p);
            }
    };

    load_kv(0, 0); CP_COMMIT();

    float sv[8][4], ov[8][4];
    #pragma unroll
    for (int j = 0; j < 8; j++)
        #pragma unroll
        for (int c = 0; c < 4; c++) ov[j][c] = 0.f;
    float rm0 = -1e30f, rm1 = -1e30f, rl0 = 0.f, rl1 = 0.f;

    const int nchunks = (ng + 63) >> 6;
    for (int c = 0; c < nchunks; c++) {
        if (c + 1 < nchunks) { load_kv((c + 1) & 1, (c + 1) * 64); CP_COMMIT(); CP_WAIT(1); }
        else                 { CP_WAIT(0); }
        __syncthreads();
        const uint32_t sK = sb + AT_B + (c & 1) * 2 * AT_B;
        const uint32_t sV = sK + AT_B;

        #pragma unroll
        for (int j = 0; j < 8; j++)
            #pragma unroll
            for (int cc = 0; cc < 4; cc++) sv[j][cc] = 0.f;
        #pragma unroll
        for (int ks = 0; ks < 4; ks++) {
            const int kk = ks * 16 + lcol;
            uint32_t qh[4];
            ldsm4(qh, sQ + (uint32_t)((w * 16 + lrow) * AP + kk) * 2);
            #pragma unroll
            for (int n16 = 0; n16 < 4; n16++) {
                uint32_t kh[4];
                ldsm4(kh, sK + (uint32_t)((n16 * 16 + lrow) * AP + kk) * 2);
                mma16816(sv[2 * n16],     qh, kh[0], kh[2]);
                mma16816(sv[2 * n16 + 1], qh, kh[1], kh[3]);
            }
        }

        const int kb = c * 64;
        #pragma unroll
        for (int j = 0; j < 8; j++) {
            int col = kb + j * 8 + (lane & 3) * 2;
            bool v0 = col < ng, v1 = (col + 1) < ng;
            sv[j][0] = v0 ? sv[j][0] * 0.125f : -1e30f;
            sv[j][1] = v1 ? sv[j][1] * 0.125f : -1e30f;
            sv[j][2] = v0 ? sv[j][2] * 0.125f : -1e30f;
            sv[j][3] = v1 ? sv[j][3] * 0.125f : -1e30f;
        }
        float m0 = -1e30f, m1 = -1e30f;
        #pragma unroll
        for (int j = 0; j < 8; j++) {
            m0 = fmaxf(m0, fmaxf(sv[j][0], sv[j][1]));
            m1 = fmaxf(m1, fmaxf(sv[j][2], sv[j][3]));
        }
        m0 = fmaxf(m0, __shfl_xor_sync(0xffffffffu, m0, 1));
        m0 = fmaxf(m0, __shfl_xor_sync(0xffffffffu, m0, 2));
        m1 = fmaxf(m1, __shfl_xor_sync(0xffffffffu, m1, 1));
        m1 = fmaxf(m1, __shfl_xor_sync(0xffffffffu, m1, 2));
        float nm0 = fmaxf(rm0, m0), nm1 = fmaxf(rm1, m1);
        float sc0 = __expf(rm0 - nm0), sc1 = __expf(rm1 - nm1);
        rm0 = nm0; rm1 = nm1;
        float l0 = 0.f, l1 = 0.f;
        #pragma unroll
        for (int j = 0; j < 8; j++) {
            sv[j][0] = __expf(sv[j][0] - nm0); l0 += sv[j][0];
            sv[j][1] = __expf(sv[j][1] - nm0); l0 += sv[j][1];
            sv[j][2] = __expf(sv[j][2] - nm1); l1 += sv[j][2];
            sv[j][3] = __expf(sv[j][3] - nm1); l1 += sv[j][3];
        }
        l0 += __shfl_xor_sync(0xffffffffu, l0, 1);
        l0 += __shfl_xor_sync(0xffffffffu, l0, 2);
        l1 += __shfl_xor_sync(0xffffffffu, l1, 1);
        l1 += __shfl_xor_sync(0xffffffffu, l1, 2);
        rl0 = rl0 * sc0 + l0;
        rl1 = rl1 * sc1 + l1;
        #pragma unroll
        for (int j = 0; j < 8; j++) {
            ov[j][0] *= sc0; ov[j][1] *= sc0;
            ov[j][2] *= sc1; ov[j][3] *= sc1;
        }

        #pragma unroll
        for (int ks = 0; ks < 4; ks++) {
            uint32_t ah[4];
            ah[0] = packhi(sv[2 * ks][0],     sv[2 * ks][1]);
            ah[1] = packhi(sv[2 * ks][2],     sv[2 * ks][3]);
            ah[2] = packhi(sv[2 * ks + 1][0], sv[2 * ks + 1][1]);
            ah[3] = packhi(sv[2 * ks + 1][2], sv[2 * ks + 1][3]);
            #pragma unroll
            for (int d16 = 0; d16 < 4; d16++) {
                uint32_t off = (uint32_t)((ks * 16 + lrow) * AP + d16 * 16 + lcol) * 2;
                uint32_t vh[4];
                ldsm4t(vh, sV + off);
                mma16816(ov[2 * d16],     ah, vh[0], vh[1]);
                mma16816(ov[2 * d16 + 1], ah, vh[2], vh[3]);
            }
        }
        __syncthreads();
    }

    const float inv0 = 1.f / rl0, inv1 = 1.f / rl1;
    const int m0r = q0 + w * 16 + (lane >> 2);
    const bool v0 = m0r < ng, v1 = (m0r + 8) < ng;
    const size_t rb0 = (size_t)(s0 + m0r) * DIM + h * DHEAD;
    const size_t rb1 = rb0 + 8 * DIM;
    #pragma unroll
    for (int j = 0; j < 8; j++) {
        int d = j * 8 + (lane & 3) * 2;
        if (v0)
            *(uint32_t*)&oout[rb0 + d] = packhi(ov[j][0] * inv0, ov[j][1] * inv0);
        if (v1)
            *(uint32_t*)&oout[rb1 + d] = packhi(ov[j][2] * inv1, ov[j][3] * inv1);
    }
}

// ======================= launch ==================================================
extern "C" void kernel_launch(void* const* d_in, const int* in_sizes, int n_in,
                              void* d_out, int out_size) {
    const float* z     = (const float*)d_in[0];
    const int*   src   = (const int*)  d_in[1];
    const float* gamma = (const float*)d_in[2];
    const float* beta  = (const float*)d_in[3];
    const float* Wq    = (const float*)d_in[4];
    const float* Wk    = (const float*)d_in[5];
    const float* Wv    = (const float*)d_in[6];
    const float* Wo    = (const float*)d_in[7];
    const float* bo    = (const float*)d_in[8];
    float* out = (float*)d_out;

    cudaFuncSetAttribute(attn_kernel, cudaFuncAttributeMaxDynamicSharedMemorySize, A_SMEM);
    cudaFuncSetAttribute(gemm_mma<0>, cudaFuncAttributeMaxDynamicSharedMemorySize, G_SMEM_TOT);
    cudaFuncSetAttribute(gemm_mma<1>, cudaFuncAttributeMaxDynamicSharedMemorySize, G_SMEM_TOT);

    __half *a_p, *wt_p, *q_p, *k_p, *v_p;
    cudaGetSymbolAddress((void**)&a_p,  g_a);
    cudaGetSymbolAddress((void**)&wt_p, g_wt);
    cudaGetSymbolAddress((void**)&q_p,  g_q);
    cudaGetSymbolAddress((void**)&k_p,  g_k);
    cudaGetSymbolAddress((void**)&v_p,  g_v);

    // fused LN + weight convert + starts
    prep_kernel<<<LN_BLOCKS + WC_BLOCKS + 1, 256>>>(z, gamma, beta, Wq, Wk, Wv, Wo, src);

    // fused Q/K/V projections (single-product fp16, cp.async 3-stage, 2 CTAs/SM)
    gemm_mma<0><<<dim3(4, 96, 3), 256, G_SMEM_TOT>>>(
        a_p, wt_p, q_p, k_p, v_p, nullptr, nullptr);

    attn_kernel<<<dim3(8, HEADS, NBATCH), 128, A_SMEM>>>(q_p, k_p, v_p, a_p);

    // output projection (fp32 + bias)
    gemm_mma<1><<<dim3(4, 96, 1), 256, G_SMEM_TOT>>>(
        a_p, wt_p + 3 * DIN * DIM,
        nullptr, nullptr, nullptr, out, bo);
}